// round 14
// baseline (speedup 1.0000x reference)
#include <cuda_runtime.h>
#include <cuda_bf16.h>
#include <math.h>

#define HW     36864
#define IMG    192
#define CCH    192
#define HIDN   768
#define NWIN   144
#define NHEAD  6
#define NTOK   256
#define KINN   128
#define TOPKN  64
#define QKVN   576

// ---------------- scratch buffers (static, no allocation) ----------------
__device__ __align__(128) float g_xn  [HW*CCH];
__device__ __align__(128) float g_sct [HW*CCH];
__device__ __align__(128) float g_qkv [HW*QKVN];
__device__ __align__(128) float g_vl  [HW*CCH];
__device__ __align__(128) float g_attn[HW*CCH];
__device__ __align__(128) float g_x2  [HW*CCH];
__device__ __align__(128) float g_yln [HW*CCH];
__device__ __align__(128) float g_yb  [HW*HIDN];
__device__ __align__(128) float g_y2  [HW*HIDN];
__device__ __align__(128) float g_wqkv[CCH*QKVN];
__device__ __align__(128) float g_bqkv[QKVN];

__device__ __forceinline__ float gelu_f(float x) {
    return 0.5f * x * (1.0f + erff(x * 0.70710678118654752f));
}

__device__ __forceinline__ unsigned smem_u32(const void* p) {
    return (unsigned)__cvta_generic_to_shared(p);
}
__device__ __forceinline__ void cp16(unsigned dst, const void* src) {
    asm volatile("cp.async.cg.shared.global [%0], [%1], 16;\n" :: "r"(dst), "l"(src));
}
__device__ __forceinline__ void cp_commit() {
    asm volatile("cp.async.commit_group;\n");
}
template<int N>
__device__ __forceinline__ void cp_wait() {
    asm volatile("cp.async.wait_group %0;\n" :: "n"(N));
}

// ---------------- QKV weight/bias concat: [192][576] ----------------
__global__ void qkv_prep_kernel(const float* __restrict__ wq, const float* __restrict__ wk,
                                const float* __restrict__ wv, const float* __restrict__ bq,
                                const float* __restrict__ bk, const float* __restrict__ bv,
                                float* __restrict__ w, float* __restrict__ b) {
    int idx = blockIdx.x * 256 + threadIdx.x;
    if (idx < CCH * QKVN) {
        int kk = idx / QKVN, n = idx % QKVN;
        float v;
        if (n < 192)      v = wq[kk * CCH + n];
        else if (n < 384) v = wk[kk * CCH + (n - 192)];
        else              v = wv[kk * CCH + (n - 384)];
        w[idx] = v;
    }
    if (idx < QKVN) {
        float v;
        if (idx < 192)      v = bq[idx];
        else if (idx < 384) v = bk[idx - 192];
        else                v = bv[idx - 384];
        b[idx] = v;
    }
}

// ---------------- LN1: transpose (C,HW)->(HW,C) + LayerNorm + raw transpose ---
#define LNP 48
__global__ void ln1_kernel(const float* __restrict__ f, const float* __restrict__ g,
                           const float* __restrict__ b, float* __restrict__ xn,
                           float* __restrict__ sct) {
    __shared__ float tile[LNP][193];
    __shared__ float mArr[LNP], rArr[LNP];
    const int t = threadIdx.x;
    const int p0 = blockIdx.x * LNP;
    for (int lin = t; lin < LNP * CCH; lin += 256) {
        int c = lin / LNP, p = lin % LNP;
        tile[p][c] = f[(size_t)c * HW + p0 + p];
    }
    __syncthreads();
    {
        int tq = t & 3, p = t >> 2;
        if (p < LNP) {
            float s = 0.f, s2 = 0.f;
            #pragma unroll 8
            for (int cc = 0; cc < 48; cc++) {
                float v = tile[p][tq * 48 + cc];
                s += v; s2 += v * v;
            }
            s  += __shfl_xor_sync(0xffffffffu, s, 1);
            s2 += __shfl_xor_sync(0xffffffffu, s2, 1);
            s  += __shfl_xor_sync(0xffffffffu, s, 2);
            s2 += __shfl_xor_sync(0xffffffffu, s2, 2);
            if (tq == 0) {
                float m = s * (1.f / CCH);
                float var = s2 * (1.f / CCH) - m * m;
                mArr[p] = m; rArr[p] = rsqrtf(var + 1e-5f);
            }
        }
    }
    __syncthreads();
    for (int lin = t; lin < LNP * CCH; lin += 256) {
        int p = lin / CCH, c = lin % CCH;
        float v = tile[p][c];
        size_t o = (size_t)(p0 + p) * CCH + c;
        sct[o] = v;
        xn[o] = (v - mArr[p]) * rArr[p] * g[c] + b[c];
    }
}

// ---------------- LN2: row-major (HW,C) LayerNorm, float4 ----------------
__global__ void ln2_kernel(const float* __restrict__ x, const float* __restrict__ g,
                           const float* __restrict__ b, float* __restrict__ y) {
    int p = blockIdx.x * 256 + threadIdx.x;
    const float4* row = (const float4*)(x + (size_t)p * CCH);
    float s = 0.f, s2 = 0.f;
    #pragma unroll
    for (int c = 0; c < CCH / 4; c++) {
        float4 v = row[c];
        s += v.x + v.y + v.z + v.w;
        s2 += v.x * v.x + v.y * v.y + v.z * v.z + v.w * v.w;
    }
    float m = s * (1.f / CCH);
    float var = s2 * (1.f / CCH) - m * m;
    float r = rsqrtf(var + 1e-5f);
    const float4* g4 = (const float4*)g;
    const float4* b4 = (const float4*)b;
    float4* orow = (float4*)(y + (size_t)p * CCH);
    #pragma unroll
    for (int c = 0; c < CCH / 4; c++) {
        float4 v = row[c], gg = g4[c], bb = b4[c], o;
        o.x = (v.x - m) * r * gg.x + bb.x;
        o.y = (v.y - m) * r * gg.y + bb.y;
        o.z = (v.z - m) * r * gg.z + bb.z;
        o.w = (v.w - m) * r * gg.w + bb.w;
        orow[c] = o;
    }
}

// ---- SGEMM v4: BM=64, BN=192, BK=16, 128 thr; B via 3-stage cp.async,
//      A via register prefetch + transposed STS -> [kk][m] (vectorized LDS) ----
#define A_ROW   68
#define A_BUF   (16 * A_ROW)            // one buffer = 1088 floats
#define BS_STRIDE 196
#define B_STAGE (16 * BS_STRIDE)        // 3136 floats
#define GEMM_SMEM_BYTES ((2 * A_BUF + 3 * B_STAGE) * 4)

template<int ACT, int RES>
__global__ void __launch_bounds__(128, 3)
sgemm_kernel(const float* __restrict__ A, const float* __restrict__ B,
             const float* __restrict__ bias, float* __restrict__ C,
             int M, int N, int K, const float* __restrict__ res) {
    extern __shared__ float sm[];
    float* As = sm;                      // 2 buffers, [kk][m] layout, row 68
    float* Bs = sm + 2 * A_BUF;          // 3 stages, [kk][n] layout
    const int tid = threadIdx.x;
    const int m0 = blockIdx.y * 64, n0 = blockIdx.x * 192;
    const int txx = tid & 15, tyy = tid >> 4;

    // A mapping: thread -> (row am, k-offset ak..ak+7)
    const int am = tid >> 1, ak = (tid & 1) * 8;
    const float* Asrc = A + (size_t)(m0 + am) * K + ak;
    // B mapping: 6 chunks
    int bk[6], bn[6];
    #pragma unroll
    for (int j = 0; j < 6; j++) {
        int lin = tid + j * 128;
        bk[j] = lin / 48; bn[j] = (lin % 48) * 4;
    }

    const int nT = K >> 4;

    auto issueB = [&](int slot, int kt) {
        if (kt < nT) {
            float* bs = Bs + slot * B_STAGE;
            #pragma unroll
            for (int j = 0; j < 6; j++) {
                unsigned db = smem_u32(bs + bk[j] * BS_STRIDE + bn[j]);
                cp16(db, B + (size_t)(kt * 16 + bk[j]) * N + n0 + bn[j]);
            }
        }
        cp_commit();
    };

    float acc[8][12];
    #pragma unroll
    for (int i = 0; i < 8; i++)
        #pragma unroll
        for (int j = 0; j < 12; j++) acc[i][j] = 0.f;

    // prologue: A tile 0 -> buf 0 (transposed), B tiles 0,1 via cp.async
    float4 a0 = *(const float4*)(Asrc);
    float4 a1 = *(const float4*)(Asrc + 4);
    {
        float* as = As;
        as[(ak + 0) * A_ROW + am] = a0.x; as[(ak + 1) * A_ROW + am] = a0.y;
        as[(ak + 2) * A_ROW + am] = a0.z; as[(ak + 3) * A_ROW + am] = a0.w;
        as[(ak + 4) * A_ROW + am] = a1.x; as[(ak + 5) * A_ROW + am] = a1.y;
        as[(ak + 6) * A_ROW + am] = a1.z; as[(ak + 7) * A_ROW + am] = a1.w;
    }
    issueB(0, 0);
    issueB(1, 1);
    cp_wait<1>();
    __syncthreads();

    for (int t = 0; t < nT; t++) {
        if (t + 1 < nT) {
            a0 = *(const float4*)(Asrc + (size_t)(t + 1) * 16);
            a1 = *(const float4*)(Asrc + (size_t)(t + 1) * 16 + 4);
        }
        const float* as = As + (t & 1) * A_BUF;
        const float* bs = Bs + (t % 3) * B_STAGE;
        #pragma unroll 4
        for (int kk = 0; kk < 16; kk++) {
            float4 A0 = *(const float4*)&as[kk * A_ROW + tyy * 4];
            float4 A1 = *(const float4*)&as[kk * A_ROW + 32 + tyy * 4];
            float4 B0 = *(const float4*)&bs[kk * BS_STRIDE + txx * 4];
            float4 B1 = *(const float4*)&bs[kk * BS_STRIDE + 64 + txx * 4];
            float4 B2 = *(const float4*)&bs[kk * BS_STRIDE + 128 + txx * 4];
            float a[8] = {A0.x, A0.y, A0.z, A0.w, A1.x, A1.y, A1.z, A1.w};
            float bb[12] = {B0.x, B0.y, B0.z, B0.w, B1.x, B1.y, B1.z, B1.w,
                            B2.x, B2.y, B2.z, B2.w};
            #pragma unroll
            for (int i = 0; i < 8; i++)
                #pragma unroll
                for (int j = 0; j < 12; j++) acc[i][j] += a[i] * bb[j];
        }
        issueB((t + 2) % 3, t + 2);
        if (t + 1 < nT) {
            float* as2 = As + ((t + 1) & 1) * A_BUF;
            as2[(ak + 0) * A_ROW + am] = a0.x; as2[(ak + 1) * A_ROW + am] = a0.y;
            as2[(ak + 2) * A_ROW + am] = a0.z; as2[(ak + 3) * A_ROW + am] = a0.w;
            as2[(ak + 4) * A_ROW + am] = a1.x; as2[(ak + 5) * A_ROW + am] = a1.y;
            as2[(ak + 6) * A_ROW + am] = a1.z; as2[(ak + 7) * A_ROW + am] = a1.w;
        }
        cp_wait<1>();
        __syncthreads();
    }

    // epilogue: rows m0 + tyy*4 + (i&3) + (i>>2)*32
    #pragma unroll
    for (int i = 0; i < 8; i++) {
        int m = m0 + tyy * 4 + (i & 3) + (i >> 2) * 32;
        #pragma unroll
        for (int jc = 0; jc < 3; jc++) {
            int n = n0 + jc * 64 + txx * 4;
            float4 o;
            o.x = acc[i][jc * 4 + 0] + bias[n + 0];
            o.y = acc[i][jc * 4 + 1] + bias[n + 1];
            o.z = acc[i][jc * 4 + 2] + bias[n + 2];
            o.w = acc[i][jc * 4 + 3] + bias[n + 3];
            if (ACT == 1) {
                o.x = gelu_f(o.x); o.y = gelu_f(o.y);
                o.z = gelu_f(o.z); o.w = gelu_f(o.w);
            }
            if (RES == 1) {
                float4 rv = *(const float4*)(res + (size_t)m * N + n);
                o.x += rv.x; o.y += rv.y; o.z += rv.z; o.w += rv.w;
            }
            *(float4*)(C + (size_t)m * N + n) = o;
        }
    }
}

// ---------------- dwconv: smem tile 8x8 px x 16 ch, 12x12 halo ----------------
// in may be a strided slice (instride floats per pixel); out is Cn-contiguous.
__global__ void dwconv_kernel(const float* __restrict__ in, int instride,
                              const float* __restrict__ wgt,
                              const float* __restrict__ bias, float* __restrict__ out,
                              int Cn, int addin) {
    __shared__ float4 tile[12 * 12 * 4];
    __shared__ float wsm[16][26];
    const int tid = threadIdx.x;
    const int c4l = tid & 3, px = (tid >> 2) & 7, py = tid >> 5;
    const int c4b = blockIdx.y;
    const int gx0 = (blockIdx.x % 24) * 8, gy0 = (blockIdx.x / 24) * 8;

    for (int lw = tid; lw < 400; lw += 256)
        wsm[lw / 25][lw % 25] = wgt[(c4b * 16 + lw / 25) * 25 + lw % 25];

    for (int lin = tid; lin < 576; lin += 256) {
        int cc = lin & 3, rem = lin >> 2;
        int xx = rem % 12, yy = rem / 12;
        int gy = gy0 + yy - 2, gx = gx0 + xx - 2;
        float4 v = make_float4(0.f, 0.f, 0.f, 0.f);
        if ((unsigned)gy < (unsigned)IMG && (unsigned)gx < (unsigned)IMG)
            v = *(const float4*)(in + (size_t)(gy * IMG + gx) * instride + (c4b * 4 + cc) * 4);
        tile[(yy * 12 + xx) * 4 + cc] = v;
    }
    __syncthreads();

    float4 a = *(const float4*)(bias + (c4b * 4 + c4l) * 4);
    #pragma unroll
    for (int ky = 0; ky < 5; ky++) {
        #pragma unroll
        for (int kx = 0; kx < 5; kx++) {
            float4 v = tile[((py + ky) * 12 + px + kx) * 4 + c4l];
            int tp = ky * 5 + kx;
            a.x += v.x * wsm[c4l * 4 + 0][tp];
            a.y += v.y * wsm[c4l * 4 + 1][tp];
            a.z += v.z * wsm[c4l * 4 + 2][tp];
            a.w += v.w * wsm[c4l * 4 + 3][tp];
        }
    }
    float4 o;
    o.x = gelu_f(a.x); o.y = gelu_f(a.y); o.z = gelu_f(a.z); o.w = gelu_f(a.w);
    if (addin) {
        float4 iv = tile[((py + 2) * 12 + px + 2) * 4 + c4l];
        o.x += iv.x; o.y += iv.y; o.z += iv.z; o.w += iv.w;
    }
    *(float4*)(out + (size_t)((gy0 + py) * IMG + gx0 + px) * Cn + (c4b * 4 + c4l) * 4) = o;
}

// ---------------- attention: one CTA per (head, window), 256 threads ----------
// smem: kv[32][256] transposed (K, restaged as V) + sc[128][256] + js(u8) = 197120 B
#define KVS 256
#define ATTN_SMEM_BYTES (32*KVS*4 + 128*256*4 + 128*260)
__global__ void attn_kernel(const float* __restrict__ qkv, const float* __restrict__ vl,
                            const float* __restrict__ pfa_v, const int* __restrict__ pfa_i,
                            const int* __restrict__ rpi, const float* __restrict__ rpb,
                            float* __restrict__ out) {
    extern __shared__ float smA[];
    float* kv = smA;                                     // [d][j] : 32 x 256
    float* sc = kv + 32 * KVS;                           // [kk][t]
    unsigned char* js = (unsigned char*)(sc + 128 * 256);  // [kk][260]

    const int t = threadIdx.x;
    const int h = blockIdx.x;
    const int w = blockIdx.y;
    const int wy = w / 12, wx = w % 12;
    const size_t whbase = ((size_t)w * NHEAD + h) * NTOK;

    const float* qg = qkv;                // stride QKVN
    const float* kg = qkv + 192;
    const float* vg = qkv + 384;

    // stage K transposed: [d][j]
    #pragma unroll
    for (int rb = 0; rb < 256; rb += 32) {
        int r = rb + (t >> 3), e = t & 7;
        int pj = (wy * 16 + (r >> 4)) * IMG + wx * 16 + (r & 15);
        float4 kvl = *(const float4*)(kg + (size_t)pj * QKVN + h * 32 + e * 4);
        kv[(e * 4 + 0) * KVS + r] = kvl.x;
        kv[(e * 4 + 1) * KVS + r] = kvl.y;
        kv[(e * 4 + 2) * KVS + r] = kvl.z;
        kv[(e * 4 + 3) * KVS + r] = kvl.w;
    }
    {
        const int* idxg = pfa_i + whbase * KINN;
        for (int e = t; e < NTOK * KINN; e += 256)
            js[(e & 127) * 260 + (e >> 7)] = (unsigned char)idxg[e];
    }
    __syncthreads();

    const int i = t;
    const int pi = (wy * 16 + (i >> 4)) * IMG + wx * 16 + (i & 15);

    float qreg[32];
    {
        const float4* qr = (const float4*)(qg + (size_t)pi * QKVN + h * 32);
        const float scl = 0.17677669529663688f;  // 1/sqrt(32)
        #pragma unroll
        for (int e = 0; e < 8; e++) {
            float4 a4 = qr[e];
            qreg[e * 4 + 0] = a4.x * scl; qreg[e * 4 + 1] = a4.y * scl;
            qreg[e * 4 + 2] = a4.z * scl; qreg[e * 4 + 3] = a4.w * scl;
        }
    }

    const int* rr = rpi + i * NTOK;
    float mx = -1e30f;
    #pragma unroll 2
    for (int kk = 0; kk < KINN; kk++) {
        int j = js[kk * 260 + t];
        float d = 0.f;
        #pragma unroll
        for (int dd = 0; dd < 32; dd++)
            d += qreg[dd] * kv[dd * KVS + j];
        d += __ldg(&rpb[__ldg(&rr[j]) * NHEAD + h]);
        sc[kk * 256 + t] = d;
        mx = fmaxf(mx, d);
    }

    float sE = 0.f;
    #pragma unroll 4
    for (int kk = 0; kk < KINN; kk++) {
        float e = __expf(sc[kk * 256 + t] - mx);
        sc[kk * 256 + t] = e;
        sE += e;
    }

    const float* pv = pfa_v + (whbase + i) * KINN;
    const float inv = 1.0f / sE;
    float sA = 0.f;
    float gmax[16];
    #pragma unroll
    for (int g = 0; g < 16; g++) {
        float gm = -3.f;
        #pragma unroll
        for (int e2 = 0; e2 < 8; e2 += 4) {
            int kk = g * 8 + e2;
            float4 p4 = *(const float4*)(pv + kk);
            float a0 = sc[(kk + 0) * 256 + t] * p4.x * inv;
            float a1 = sc[(kk + 1) * 256 + t] * p4.y * inv;
            float a2 = sc[(kk + 2) * 256 + t] * p4.z * inv;
            float a3 = sc[(kk + 3) * 256 + t] * p4.w * inv;
            sc[(kk + 0) * 256 + t] = a0; sc[(kk + 1) * 256 + t] = a1;
            sc[(kk + 2) * 256 + t] = a2; sc[(kk + 3) * 256 + t] = a3;
            sA += a0 + a1 + a2 + a3;
            gm = fmaxf(gm, fmaxf(fmaxf(a0, a1), fmaxf(a2, a3)));
        }
        gmax[g] = gm;
    }
    const float r2 = 1.0f / (sA + 1e-10f);

    // restage V over the K buffer (same transposed layout)
    __syncthreads();
    #pragma unroll
    for (int rb = 0; rb < 256; rb += 32) {
        int r = rb + (t >> 3), e = t & 7;
        int pj = (wy * 16 + (r >> 4)) * IMG + wx * 16 + (r & 15);
        float4 vv4 = *(const float4*)(vg + (size_t)pj * QKVN + h * 32 + e * 4);
        kv[(e * 4 + 0) * KVS + r] = vv4.x;
        kv[(e * 4 + 1) * KVS + r] = vv4.y;
        kv[(e * 4 + 2) * KVS + r] = vv4.z;
        kv[(e * 4 + 3) * KVS + r] = vv4.w;
    }
    __syncthreads();

    float acc[32];
    #pragma unroll
    for (int dd = 0; dd < 32; dd++) acc[dd] = 0.f;
    for (int sel = 0; sel < TOPKN; sel++) {
        float best = gmax[0]; int bg = 0;
        #pragma unroll
        for (int g = 1; g < 16; g++)
            if (gmax[g] > best) { best = gmax[g]; bg = g; }
        float m1 = -3.f, m2 = -3.f; int be = 0;
        #pragma unroll
        for (int e2 = 0; e2 < 8; e2++) {
            float vv = sc[(bg * 8 + e2) * 256 + t];
            if (vv > m1) { m2 = m1; m1 = vv; be = e2; }
            else m2 = fmaxf(m2, vv);
        }
        int bkk = bg * 8 + be;
        sc[bkk * 256 + t] = -3.f;
        #pragma unroll
        for (int g = 0; g < 16; g++) if (g == bg) gmax[g] = m2;

        int j = js[bkk * 260 + t];
        float wv = (m1 + 1e-10f) * r2;
        #pragma unroll
        for (int dd = 0; dd < 32; dd++)
            acc[dd] += wv * kv[dd * KVS + j];
    }

    float* op = out + (size_t)pi * CCH + h * 32;
    const float* vp = vl + (size_t)pi * CCH + h * 32;
    #pragma unroll
    for (int e = 0; e < 8; e++) {
        float4 o;
        o.x = acc[e * 4 + 0] + vp[e * 4 + 0];
        o.y = acc[e * 4 + 1] + vp[e * 4 + 1];
        o.z = acc[e * 4 + 2] + vp[e * 4 + 2];
        o.w = acc[e * 4 + 3] + vp[e * 4 + 3];
        *(float4*)(op + e * 4) = o;
    }
}

// ---------------- launch ----------------
extern "C" void kernel_launch(void* const* d_in, const int* in_sizes, int n_in,
                              void* d_out, int out_size) {
    const float* features = (const float*)d_in[0];
    const float* pfa_v    = (const float*)d_in[1];
    const int*   pfa_i    = (const int*)  d_in[2];
    const int*   rpi      = (const int*)  d_in[3];
    const float* ln1_g    = (const float*)d_in[4];
    const float* ln1_b    = (const float*)d_in[5];
    const float* Wq_w     = (const float*)d_in[6];
    const float* Wq_b     = (const float*)d_in[7];
    const float* Wk_w     = (const float*)d_in[8];
    const float* Wk_b     = (const float*)d_in[9];
    const float* Wv_w     = (const float*)d_in[10];
    const float* Wv_b     = (const float*)d_in[11];
    const float* lepe_w   = (const float*)d_in[12];
    const float* lepe_b   = (const float*)d_in[13];
    const float* rpb_tab  = (const float*)d_in[14];
    const float* proj_w   = (const float*)d_in[15];
    const float* proj_b   = (const float*)d_in[16];
    const float* ln2_g    = (const float*)d_in[17];
    const float* ln2_b    = (const float*)d_in[18];
    const float* fc1_w    = (const float*)d_in[19];
    const float* fc1_b    = (const float*)d_in[20];
    const float* ffn_dw_w = (const float*)d_in[21];
    const float* ffn_dw_b = (const float*)d_in[22];
    const float* fc2_w    = (const float*)d_in[23];
    const float* fc2_b    = (const float*)d_in[24];
    float* outp = (float*)d_out;

    float *xn, *sct, *qkvb, *vlb, *attnb, *x2b, *ylnb, *ybb, *y2b, *wqkv, *bqkv;
    cudaGetSymbolAddress((void**)&xn,    g_xn);
    cudaGetSymbolAddress((void**)&sct,   g_sct);
    cudaGetSymbolAddress((void**)&qkvb,  g_qkv);
    cudaGetSymbolAddress((void**)&vlb,   g_vl);
    cudaGetSymbolAddress((void**)&attnb, g_attn);
    cudaGetSymbolAddress((void**)&x2b,   g_x2);
    cudaGetSymbolAddress((void**)&ylnb,  g_yln);
    cudaGetSymbolAddress((void**)&ybb,   g_yb);
    cudaGetSymbolAddress((void**)&y2b,   g_y2);
    cudaGetSymbolAddress((void**)&wqkv,  g_wqkv);
    cudaGetSymbolAddress((void**)&bqkv,  g_bqkv);

    cudaFuncSetAttribute(attn_kernel, cudaFuncAttributeMaxDynamicSharedMemorySize,
                         ATTN_SMEM_BYTES);
    cudaFuncSetAttribute(sgemm_kernel<0, 0>, cudaFuncAttributeMaxDynamicSharedMemorySize,
                         GEMM_SMEM_BYTES);
    cudaFuncSetAttribute(sgemm_kernel<0, 1>, cudaFuncAttributeMaxDynamicSharedMemorySize,
                         GEMM_SMEM_BYTES);
    cudaFuncSetAttribute(sgemm_kernel<1, 0>, cudaFuncAttributeMaxDynamicSharedMemorySize,
                         GEMM_SMEM_BYTES);

    const int M = HW;

    // 0) concat QKV weights/biases
    qkv_prep_kernel<<<(CCH * QKVN + 255) / 256, 256>>>(Wq_w, Wk_w, Wv_w,
                                                       Wq_b, Wk_b, Wv_b, wqkv, bqkv);

    // 1) transpose + LN1 (+ raw transposed shortcut)
    ln1_kernel<<<HW / LNP, 256>>>(features, ln1_g, ln1_b, xn, sct);

    // 2) fused QKV projection: (HW,192) @ (192,576)
    sgemm_kernel<0, 0><<<dim3(3, M / 64), 128, GEMM_SMEM_BYTES>>>(
        xn, wqkv, bqkv, qkvb, M, QKVN, CCH, nullptr);

    // 3) LePE: depthwise 5x5 + GELU on V slice of qkv
    dwconv_kernel<<<dim3(576, CCH / 16), 256>>>(qkvb + 384, QKVN, lepe_w, lepe_b,
                                                vlb, CCH, 0);

    // 4) sparse windowed attention (+vl)
    attn_kernel<<<dim3(NHEAD, NWIN), 256, ATTN_SMEM_BYTES>>>(
        qkvb, vlb, pfa_v, pfa_i, rpi, rpb_tab, attnb);

    // 5) output projection + shortcut (coalesced transposed residual)
    dim3 g192(1, M / 64);
    sgemm_kernel<0, 1><<<g192, 128, GEMM_SMEM_BYTES>>>(attnb, proj_w, proj_b, x2b,
                                                       M, CCH, CCH, sct);

    // 6) ConvFFN
    ln2_kernel<<<HW / 256, 256>>>(x2b, ln2_g, ln2_b, ylnb);
    sgemm_kernel<1, 0><<<dim3(4, M / 64), 128, GEMM_SMEM_BYTES>>>(
        ylnb, fc1_w, fc1_b, ybb, M, HIDN, CCH, nullptr);
    dwconv_kernel<<<dim3(576, HIDN / 16), 256>>>(ybb, HIDN, ffn_dw_w, ffn_dw_b,
                                                 y2b, HIDN, 1);
    sgemm_kernel<0, 1><<<g192, 128, GEMM_SMEM_BYTES>>>(y2b, fc2_w, fc2_b, outp,
                                                       M, CCH, HIDN, x2b);
    (void)in_sizes; (void)n_in; (void)out_size;
}

// round 15
// speedup vs baseline: 1.0516x; 1.0516x over previous
#include <cuda_runtime.h>
#include <cuda_bf16.h>
#include <cuda_fp16.h>
#include <math.h>

#define HW     36864
#define IMG    192
#define CCH    192
#define HIDN   768
#define NWIN   144
#define NHEAD  6
#define NTOK   256
#define KINN   128
#define TOPKN  64
#define QKVN   576

// ---------------- scratch buffers (static, no allocation) ----------------
__device__ __align__(128) float g_xn  [HW*CCH];
__device__ __align__(128) float g_sct [HW*CCH];
__device__ __align__(128) float g_qkv [HW*QKVN];
__device__ __align__(128) float g_vl  [HW*CCH];
__device__ __align__(128) float g_attn[HW*CCH];
__device__ __align__(128) float g_x2  [HW*CCH];
__device__ __align__(128) float g_yln [HW*CCH];
__device__ __align__(128) float g_yb  [HW*HIDN];
__device__ __align__(128) float g_y2  [HW*HIDN];
__device__ __align__(128) float g_wqkv[CCH*QKVN];
__device__ __align__(128) float g_bqkv[QKVN];

__device__ __forceinline__ float gelu_f(float x) {
    return 0.5f * x * (1.0f + erff(x * 0.70710678118654752f));
}

__device__ __forceinline__ unsigned smem_u32(const void* p) {
    return (unsigned)__cvta_generic_to_shared(p);
}
__device__ __forceinline__ void cp16(unsigned dst, const void* src) {
    asm volatile("cp.async.cg.shared.global [%0], [%1], 16;\n" :: "r"(dst), "l"(src));
}
__device__ __forceinline__ void cp_commit() {
    asm volatile("cp.async.commit_group;\n");
}
template<int N>
__device__ __forceinline__ void cp_wait() {
    asm volatile("cp.async.wait_group %0;\n" :: "n"(N));
}

// ---------------- QKV weight/bias concat: [192][576] ----------------
__global__ void qkv_prep_kernel(const float* __restrict__ wq, const float* __restrict__ wk,
                                const float* __restrict__ wv, const float* __restrict__ bq,
                                const float* __restrict__ bk, const float* __restrict__ bv,
                                float* __restrict__ w, float* __restrict__ b) {
    int idx = blockIdx.x * 256 + threadIdx.x;
    if (idx < CCH * QKVN) {
        int kk = idx / QKVN, n = idx % QKVN;
        float v;
        if (n < 192)      v = wq[kk * CCH + n];
        else if (n < 384) v = wk[kk * CCH + (n - 192)];
        else              v = wv[kk * CCH + (n - 384)];
        w[idx] = v;
    }
    if (idx < QKVN) {
        float v;
        if (idx < 192)      v = bq[idx];
        else if (idx < 384) v = bk[idx - 192];
        else                v = bv[idx - 384];
        b[idx] = v;
    }
}

// ---------------- LN1: transpose (C,HW)->(HW,C) + LayerNorm + raw transpose ---
#define LNP 48
__global__ void ln1_kernel(const float* __restrict__ f, const float* __restrict__ g,
                           const float* __restrict__ b, float* __restrict__ xn,
                           float* __restrict__ sct) {
    __shared__ float tile[LNP][193];
    __shared__ float mArr[LNP], rArr[LNP];
    const int t = threadIdx.x;
    const int p0 = blockIdx.x * LNP;
    for (int lin = t; lin < LNP * CCH; lin += 256) {
        int c = lin / LNP, p = lin % LNP;
        tile[p][c] = f[(size_t)c * HW + p0 + p];
    }
    __syncthreads();
    {
        int tq = t & 3, p = t >> 2;
        if (p < LNP) {
            float s = 0.f, s2 = 0.f;
            #pragma unroll 8
            for (int cc = 0; cc < 48; cc++) {
                float v = tile[p][tq * 48 + cc];
                s += v; s2 += v * v;
            }
            s  += __shfl_xor_sync(0xffffffffu, s, 1);
            s2 += __shfl_xor_sync(0xffffffffu, s2, 1);
            s  += __shfl_xor_sync(0xffffffffu, s, 2);
            s2 += __shfl_xor_sync(0xffffffffu, s2, 2);
            if (tq == 0) {
                float m = s * (1.f / CCH);
                float var = s2 * (1.f / CCH) - m * m;
                mArr[p] = m; rArr[p] = rsqrtf(var + 1e-5f);
            }
        }
    }
    __syncthreads();
    for (int lin = t; lin < LNP * CCH; lin += 256) {
        int p = lin / CCH, c = lin % CCH;
        float v = tile[p][c];
        size_t o = (size_t)(p0 + p) * CCH + c;
        sct[o] = v;
        xn[o] = (v - mArr[p]) * rArr[p] * g[c] + b[c];
    }
}

// ---------------- LN2: row-major (HW,C) LayerNorm, float4 ----------------
__global__ void ln2_kernel(const float* __restrict__ x, const float* __restrict__ g,
                           const float* __restrict__ b, float* __restrict__ y) {
    int p = blockIdx.x * 256 + threadIdx.x;
    const float4* row = (const float4*)(x + (size_t)p * CCH);
    float s = 0.f, s2 = 0.f;
    #pragma unroll
    for (int c = 0; c < CCH / 4; c++) {
        float4 v = row[c];
        s += v.x + v.y + v.z + v.w;
        s2 += v.x * v.x + v.y * v.y + v.z * v.z + v.w * v.w;
    }
    float m = s * (1.f / CCH);
    float var = s2 * (1.f / CCH) - m * m;
    float r = rsqrtf(var + 1e-5f);
    const float4* g4 = (const float4*)g;
    const float4* b4 = (const float4*)b;
    float4* orow = (float4*)(y + (size_t)p * CCH);
    #pragma unroll
    for (int c = 0; c < CCH / 4; c++) {
        float4 v = row[c], gg = g4[c], bb = b4[c], o;
        o.x = (v.x - m) * r * gg.x + bb.x;
        o.y = (v.y - m) * r * gg.y + bb.y;
        o.z = (v.z - m) * r * gg.z + bb.z;
        o.w = (v.w - m) * r * gg.w + bb.w;
        orow[c] = o;
    }
}

// ---- SGEMM v4: BM=64, BN=192, BK=16, 128 thr; B via 3-stage cp.async,
//      A via register prefetch + transposed STS -> [kk][m] (vectorized LDS) ----
#define A_ROW   68
#define A_BUF   (16 * A_ROW)
#define BS_STRIDE 196
#define B_STAGE (16 * BS_STRIDE)
#define GEMM_SMEM_BYTES ((2 * A_BUF + 3 * B_STAGE) * 4)

template<int ACT, int RES>
__global__ void __launch_bounds__(128, 3)
sgemm_kernel(const float* __restrict__ A, const float* __restrict__ B,
             const float* __restrict__ bias, float* __restrict__ C,
             int M, int N, int K, const float* __restrict__ res) {
    extern __shared__ float sm[];
    float* As = sm;
    float* Bs = sm + 2 * A_BUF;
    const int tid = threadIdx.x;
    const int m0 = blockIdx.y * 64, n0 = blockIdx.x * 192;
    const int txx = tid & 15, tyy = tid >> 4;

    const int am = tid >> 1, ak = (tid & 1) * 8;
    const float* Asrc = A + (size_t)(m0 + am) * K + ak;
    int bk[6], bn[6];
    #pragma unroll
    for (int j = 0; j < 6; j++) {
        int lin = tid + j * 128;
        bk[j] = lin / 48; bn[j] = (lin % 48) * 4;
    }

    const int nT = K >> 4;

    auto issueB = [&](int slot, int kt) {
        if (kt < nT) {
            float* bs = Bs + slot * B_STAGE;
            #pragma unroll
            for (int j = 0; j < 6; j++) {
                unsigned db = smem_u32(bs + bk[j] * BS_STRIDE + bn[j]);
                cp16(db, B + (size_t)(kt * 16 + bk[j]) * N + n0 + bn[j]);
            }
        }
        cp_commit();
    };

    float acc[8][12];
    #pragma unroll
    for (int i = 0; i < 8; i++)
        #pragma unroll
        for (int j = 0; j < 12; j++) acc[i][j] = 0.f;

    float4 a0 = *(const float4*)(Asrc);
    float4 a1 = *(const float4*)(Asrc + 4);
    {
        float* as = As;
        as[(ak + 0) * A_ROW + am] = a0.x; as[(ak + 1) * A_ROW + am] = a0.y;
        as[(ak + 2) * A_ROW + am] = a0.z; as[(ak + 3) * A_ROW + am] = a0.w;
        as[(ak + 4) * A_ROW + am] = a1.x; as[(ak + 5) * A_ROW + am] = a1.y;
        as[(ak + 6) * A_ROW + am] = a1.z; as[(ak + 7) * A_ROW + am] = a1.w;
    }
    issueB(0, 0);
    issueB(1, 1);
    cp_wait<1>();
    __syncthreads();

    for (int t = 0; t < nT; t++) {
        if (t + 1 < nT) {
            a0 = *(const float4*)(Asrc + (size_t)(t + 1) * 16);
            a1 = *(const float4*)(Asrc + (size_t)(t + 1) * 16 + 4);
        }
        const float* as = As + (t & 1) * A_BUF;
        const float* bs = Bs + (t % 3) * B_STAGE;
        #pragma unroll 4
        for (int kk = 0; kk < 16; kk++) {
            float4 A0 = *(const float4*)&as[kk * A_ROW + tyy * 4];
            float4 A1 = *(const float4*)&as[kk * A_ROW + 32 + tyy * 4];
            float4 B0 = *(const float4*)&bs[kk * BS_STRIDE + txx * 4];
            float4 B1 = *(const float4*)&bs[kk * BS_STRIDE + 64 + txx * 4];
            float4 B2 = *(const float4*)&bs[kk * BS_STRIDE + 128 + txx * 4];
            float a[8] = {A0.x, A0.y, A0.z, A0.w, A1.x, A1.y, A1.z, A1.w};
            float bb[12] = {B0.x, B0.y, B0.z, B0.w, B1.x, B1.y, B1.z, B1.w,
                            B2.x, B2.y, B2.z, B2.w};
            #pragma unroll
            for (int i = 0; i < 8; i++)
                #pragma unroll
                for (int j = 0; j < 12; j++) acc[i][j] += a[i] * bb[j];
        }
        issueB((t + 2) % 3, t + 2);
        if (t + 1 < nT) {
            float* as2 = As + ((t + 1) & 1) * A_BUF;
            as2[(ak + 0) * A_ROW + am] = a0.x; as2[(ak + 1) * A_ROW + am] = a0.y;
            as2[(ak + 2) * A_ROW + am] = a0.z; as2[(ak + 3) * A_ROW + am] = a0.w;
            as2[(ak + 4) * A_ROW + am] = a1.x; as2[(ak + 5) * A_ROW + am] = a1.y;
            as2[(ak + 6) * A_ROW + am] = a1.z; as2[(ak + 7) * A_ROW + am] = a1.w;
        }
        cp_wait<1>();
        __syncthreads();
    }

    #pragma unroll
    for (int i = 0; i < 8; i++) {
        int m = m0 + tyy * 4 + (i & 3) + (i >> 2) * 32;
        #pragma unroll
        for (int jc = 0; jc < 3; jc++) {
            int n = n0 + jc * 64 + txx * 4;
            float4 o;
            o.x = acc[i][jc * 4 + 0] + bias[n + 0];
            o.y = acc[i][jc * 4 + 1] + bias[n + 1];
            o.z = acc[i][jc * 4 + 2] + bias[n + 2];
            o.w = acc[i][jc * 4 + 3] + bias[n + 3];
            if (ACT == 1) {
                o.x = gelu_f(o.x); o.y = gelu_f(o.y);
                o.z = gelu_f(o.z); o.w = gelu_f(o.w);
            }
            if (RES == 1) {
                float4 rv = *(const float4*)(res + (size_t)m * N + n);
                o.x += rv.x; o.y += rv.y; o.z += rv.z; o.w += rv.w;
            }
            *(float4*)(C + (size_t)m * N + n) = o;
        }
    }
}

// ---------------- dwconv: smem tile 8x8 px x 16 ch, 12x12 halo ----------------
__global__ void dwconv_kernel(const float* __restrict__ in, int instride,
                              const float* __restrict__ wgt,
                              const float* __restrict__ bias, float* __restrict__ out,
                              int Cn, int addin) {
    __shared__ float4 tile[12 * 12 * 4];
    __shared__ float wsm[16][26];
    const int tid = threadIdx.x;
    const int c4l = tid & 3, px = (tid >> 2) & 7, py = tid >> 5;
    const int c4b = blockIdx.y;
    const int gx0 = (blockIdx.x % 24) * 8, gy0 = (blockIdx.x / 24) * 8;

    for (int lw = tid; lw < 400; lw += 256)
        wsm[lw / 25][lw % 25] = wgt[(c4b * 16 + lw / 25) * 25 + lw % 25];

    for (int lin = tid; lin < 576; lin += 256) {
        int cc = lin & 3, rem = lin >> 2;
        int xx = rem % 12, yy = rem / 12;
        int gy = gy0 + yy - 2, gx = gx0 + xx - 2;
        float4 v = make_float4(0.f, 0.f, 0.f, 0.f);
        if ((unsigned)gy < (unsigned)IMG && (unsigned)gx < (unsigned)IMG)
            v = *(const float4*)(in + (size_t)(gy * IMG + gx) * instride + (c4b * 4 + cc) * 4);
        tile[(yy * 12 + xx) * 4 + cc] = v;
    }
    __syncthreads();

    float4 a = *(const float4*)(bias + (c4b * 4 + c4l) * 4);
    #pragma unroll
    for (int ky = 0; ky < 5; ky++) {
        #pragma unroll
        for (int kx = 0; kx < 5; kx++) {
            float4 v = tile[((py + ky) * 12 + px + kx) * 4 + c4l];
            int tp = ky * 5 + kx;
            a.x += v.x * wsm[c4l * 4 + 0][tp];
            a.y += v.y * wsm[c4l * 4 + 1][tp];
            a.z += v.z * wsm[c4l * 4 + 2][tp];
            a.w += v.w * wsm[c4l * 4 + 3][tp];
        }
    }
    float4 o;
    o.x = gelu_f(a.x); o.y = gelu_f(a.y); o.z = gelu_f(a.z); o.w = gelu_f(a.w);
    if (addin) {
        float4 iv = tile[((py + 2) * 12 + px + 2) * 4 + c4l];
        o.x += iv.x; o.y += iv.y; o.z += iv.z; o.w += iv.w;
    }
    *(float4*)(out + (size_t)((gy0 + py) * IMG + gx0 + px) * Cn + (c4b * 4 + c4l) * 4) = o;
}

// ---------------- attention v3: fp16 K/V smem, merged softmax/prior ----------
// smem: kh/vh half2 [16][KHS] + sc f32 [128][256] + js u8 [128][260] = 197376 B
#define KHS 258
#define ATTN_SMEM_BYTES (2*16*KHS*4 + 128*256*4 + 128*260)
__global__ void attn_kernel(const float* __restrict__ qkv, const float* __restrict__ vl,
                            const float* __restrict__ pfa_v, const int* __restrict__ pfa_i,
                            const int* __restrict__ rpi, const float* __restrict__ rpb,
                            float* __restrict__ out) {
    extern __shared__ char smA[];
    __half2* kh = (__half2*)smA;                           // [p][j], stride KHS
    __half2* vh = kh + 16 * KHS;
    float* sc = (float*)(vh + 16 * KHS);                   // [kk][t]
    unsigned char* js = (unsigned char*)(sc + 128 * 256);  // [kk][260]

    const int t = threadIdx.x;
    const int h = blockIdx.x;
    const int w = blockIdx.y;
    const int wy = w / 12, wx = w % 12;
    const size_t whbase = ((size_t)w * NHEAD + h) * NTOK;

    const float* qg = qkv;
    const float* kg = qkv + 192;
    const float* vg = qkv + 384;

    // stage K and V as half2, transposed [p][j]; store banks conflict-free
    #pragma unroll
    for (int rb = 0; rb < 256; rb += 32) {
        int r = rb + (t >> 3), e = t & 7;
        int pj = (wy * 16 + (r >> 4)) * IMG + wx * 16 + (r & 15);
        float4 kvl = *(const float4*)(kg + (size_t)pj * QKVN + h * 32 + e * 4);
        kh[(2 * e + 0) * KHS + r] = __floats2half2_rn(kvl.x, kvl.y);
        kh[(2 * e + 1) * KHS + r] = __floats2half2_rn(kvl.z, kvl.w);
        float4 vv4 = *(const float4*)(vg + (size_t)pj * QKVN + h * 32 + e * 4);
        vh[(2 * e + 0) * KHS + r] = __floats2half2_rn(vv4.x, vv4.y);
        vh[(2 * e + 1) * KHS + r] = __floats2half2_rn(vv4.z, vv4.w);
    }
    {
        const int* idxg = pfa_i + whbase * KINN;
        for (int e = t; e < NTOK * KINN; e += 256)
            js[(e & 127) * 260 + (e >> 7)] = (unsigned char)idxg[e];
    }
    __syncthreads();

    const int i = t;
    const int pi = (wy * 16 + (i >> 4)) * IMG + wx * 16 + (i & 15);

    float qreg[32];
    {
        const float4* qr = (const float4*)(qg + (size_t)pi * QKVN + h * 32);
        const float scl = 0.17677669529663688f;  // 1/sqrt(32)
        #pragma unroll
        for (int e = 0; e < 8; e++) {
            float4 a4 = qr[e];
            qreg[e * 4 + 0] = a4.x * scl; qreg[e * 4 + 1] = a4.y * scl;
            qreg[e * 4 + 2] = a4.z * scl; qreg[e * 4 + 3] = a4.w * scl;
        }
    }

    // gathered scores (fp16 K) + rpb
    const int* rr = rpi + i * NTOK;
    float mx = -1e30f;
    #pragma unroll 2
    for (int kk = 0; kk < KINN; kk++) {
        int j = js[kk * 260 + t];
        float d = 0.f;
        #pragma unroll
        for (int p = 0; p < 16; p++) {
            float2 f = __half22float2(kh[p * KHS + j]);
            d += qreg[2 * p] * f.x + qreg[2 * p + 1] * f.y;
        }
        d += __ldg(&rpb[__ldg(&rr[j]) * NHEAD + h]);
        sc[kk * 256 + t] = d;
        mx = fmaxf(mx, d);
    }

    // merged pass: u = exp(d-mx)*prior; track sE, sU, group maxima
    const float* pv = pfa_v + (whbase + i) * KINN;
    float sE = 0.f, sU = 0.f;
    float gmax[16];
    #pragma unroll
    for (int g = 0; g < 16; g++) {
        float gm = -3.f;
        #pragma unroll
        for (int e2 = 0; e2 < 8; e2 += 4) {
            int kk = g * 8 + e2;
            float4 p4 = *(const float4*)(pv + kk);
            float e0 = __expf(sc[(kk + 0) * 256 + t] - mx);
            float e1 = __expf(sc[(kk + 1) * 256 + t] - mx);
            float e2f = __expf(sc[(kk + 2) * 256 + t] - mx);
            float e3 = __expf(sc[(kk + 3) * 256 + t] - mx);
            sE += e0 + e1 + e2f + e3;
            float u0 = e0 * p4.x, u1 = e1 * p4.y, u2 = e2f * p4.z, u3 = e3 * p4.w;
            sc[(kk + 0) * 256 + t] = u0; sc[(kk + 1) * 256 + t] = u1;
            sc[(kk + 2) * 256 + t] = u2; sc[(kk + 3) * 256 + t] = u3;
            sU += u0 + u1 + u2 + u3;
            gm = fmaxf(gm, fmaxf(fmaxf(u0, u1), fmaxf(u2, u3)));
        }
        gmax[g] = gm;
    }
    // final weight = (u + eps*sE)/(sU + eps*sE)  ==  (u/sE + eps)/(sU/sE + eps)
    const float epsE = 1e-10f * sE;
    const float r2 = 1.0f / (sU + epsE);

    // top-64 grouped argmax (first-index-wins) fused with sparse AV (fp16 V)
    float acc[32];
    #pragma unroll
    for (int dd = 0; dd < 32; dd++) acc[dd] = 0.f;
    for (int sel = 0; sel < TOPKN; sel++) {
        float best = gmax[0]; int bg = 0;
        #pragma unroll
        for (int g = 1; g < 16; g++)
            if (gmax[g] > best) { best = gmax[g]; bg = g; }
        float m1 = -3.f, m2 = -3.f; int be = 0;
        #pragma unroll
        for (int e2 = 0; e2 < 8; e2++) {
            float vv = sc[(bg * 8 + e2) * 256 + t];
            if (vv > m1) { m2 = m1; m1 = vv; be = e2; }
            else m2 = fmaxf(m2, vv);
        }
        int bkk = bg * 8 + be;
        sc[bkk * 256 + t] = -3.f;
        #pragma unroll
        for (int g = 0; g < 16; g++) if (g == bg) gmax[g] = m2;

        int j = js[bkk * 260 + t];
        float wv = (m1 + epsE) * r2;
        #pragma unroll
        for (int p = 0; p < 16; p++) {
            float2 f = __half22float2(vh[p * KHS + j]);
            acc[2 * p] += wv * f.x;
            acc[2 * p + 1] += wv * f.y;
        }
    }

    float* op = out + (size_t)pi * CCH + h * 32;
    const float* vp = vl + (size_t)pi * CCH + h * 32;
    #pragma unroll
    for (int e = 0; e < 8; e++) {
        float4 o;
        o.x = acc[e * 4 + 0] + vp[e * 4 + 0];
        o.y = acc[e * 4 + 1] + vp[e * 4 + 1];
        o.z = acc[e * 4 + 2] + vp[e * 4 + 2];
        o.w = acc[e * 4 + 3] + vp[e * 4 + 3];
        *(float4*)(op + e * 4) = o;
    }
}

// ---------------- launch ----------------
extern "C" void kernel_launch(void* const* d_in, const int* in_sizes, int n_in,
                              void* d_out, int out_size) {
    const float* features = (const float*)d_in[0];
    const float* pfa_v    = (const float*)d_in[1];
    const int*   pfa_i    = (const int*)  d_in[2];
    const int*   rpi      = (const int*)  d_in[3];
    const float* ln1_g    = (const float*)d_in[4];
    const float* ln1_b    = (const float*)d_in[5];
    const float* Wq_w     = (const float*)d_in[6];
    const float* Wq_b     = (const float*)d_in[7];
    const float* Wk_w     = (const float*)d_in[8];
    const float* Wk_b     = (const float*)d_in[9];
    const float* Wv_w     = (const float*)d_in[10];
    const float* Wv_b     = (const float*)d_in[11];
    const float* lepe_w   = (const float*)d_in[12];
    const float* lepe_b   = (const float*)d_in[13];
    const float* rpb_tab  = (const float*)d_in[14];
    const float* proj_w   = (const float*)d_in[15];
    const float* proj_b   = (const float*)d_in[16];
    const float* ln2_g    = (const float*)d_in[17];
    const float* ln2_b    = (const float*)d_in[18];
    const float* fc1_w    = (const float*)d_in[19];
    const float* fc1_b    = (const float*)d_in[20];
    const float* ffn_dw_w = (const float*)d_in[21];
    const float* ffn_dw_b = (const float*)d_in[22];
    const float* fc2_w    = (const float*)d_in[23];
    const float* fc2_b    = (const float*)d_in[24];
    float* outp = (float*)d_out;

    float *xn, *sct, *qkvb, *vlb, *attnb, *x2b, *ylnb, *ybb, *y2b, *wqkv, *bqkv;
    cudaGetSymbolAddress((void**)&xn,    g_xn);
    cudaGetSymbolAddress((void**)&sct,   g_sct);
    cudaGetSymbolAddress((void**)&qkvb,  g_qkv);
    cudaGetSymbolAddress((void**)&vlb,   g_vl);
    cudaGetSymbolAddress((void**)&attnb, g_attn);
    cudaGetSymbolAddress((void**)&x2b,   g_x2);
    cudaGetSymbolAddress((void**)&ylnb,  g_yln);
    cudaGetSymbolAddress((void**)&ybb,   g_yb);
    cudaGetSymbolAddress((void**)&y2b,   g_y2);
    cudaGetSymbolAddress((void**)&wqkv,  g_wqkv);
    cudaGetSymbolAddress((void**)&bqkv,  g_bqkv);

    cudaFuncSetAttribute(attn_kernel, cudaFuncAttributeMaxDynamicSharedMemorySize,
                         ATTN_SMEM_BYTES);
    cudaFuncSetAttribute(sgemm_kernel<0, 0>, cudaFuncAttributeMaxDynamicSharedMemorySize,
                         GEMM_SMEM_BYTES);
    cudaFuncSetAttribute(sgemm_kernel<0, 1>, cudaFuncAttributeMaxDynamicSharedMemorySize,
                         GEMM_SMEM_BYTES);
    cudaFuncSetAttribute(sgemm_kernel<1, 0>, cudaFuncAttributeMaxDynamicSharedMemorySize,
                         GEMM_SMEM_BYTES);

    const int M = HW;

    // 0) concat QKV weights/biases
    qkv_prep_kernel<<<(CCH * QKVN + 255) / 256, 256>>>(Wq_w, Wk_w, Wv_w,
                                                       Wq_b, Wk_b, Wv_b, wqkv, bqkv);

    // 1) transpose + LN1 (+ raw transposed shortcut)
    ln1_kernel<<<HW / LNP, 256>>>(features, ln1_g, ln1_b, xn, sct);

    // 2) fused QKV projection: (HW,192) @ (192,576)
    sgemm_kernel<0, 0><<<dim3(3, M / 64), 128, GEMM_SMEM_BYTES>>>(
        xn, wqkv, bqkv, qkvb, M, QKVN, CCH, nullptr);

    // 3) LePE: depthwise 5x5 + GELU on V slice of qkv
    dwconv_kernel<<<dim3(576, CCH / 16), 256>>>(qkvb + 384, QKVN, lepe_w, lepe_b,
                                                vlb, CCH, 0);

    // 4) sparse windowed attention (+vl)
    attn_kernel<<<dim3(NHEAD, NWIN), 256, ATTN_SMEM_BYTES>>>(
        qkvb, vlb, pfa_v, pfa_i, rpi, rpb_tab, attnb);

    // 5) output projection + shortcut (coalesced transposed residual)
    dim3 g192(1, M / 64);
    sgemm_kernel<0, 1><<<g192, 128, GEMM_SMEM_BYTES>>>(attnb, proj_w, proj_b, x2b,
                                                       M, CCH, CCH, sct);

    // 6) ConvFFN
    ln2_kernel<<<HW / 256, 256>>>(x2b, ln2_g, ln2_b, ylnb);
    sgemm_kernel<1, 0><<<dim3(4, M / 64), 128, GEMM_SMEM_BYTES>>>(
        ylnb, fc1_w, fc1_b, ybb, M, HIDN, CCH, nullptr);
    dwconv_kernel<<<dim3(576, HIDN / 16), 256>>>(ybb, HIDN, ffn_dw_w, ffn_dw_b,
                                                 y2b, HIDN, 1);
    sgemm_kernel<0, 1><<<g192, 128, GEMM_SMEM_BYTES>>>(y2b, fc2_w, fc2_b, outp,
                                                       M, CCH, HIDN, x2b);
    (void)in_sizes; (void)n_in; (void)out_size;
}

// round 16
// speedup vs baseline: 1.4709x; 1.3988x over previous
#include <cuda_runtime.h>
#include <cuda_bf16.h>
#include <cuda_fp16.h>
#include <math.h>

#define HW     36864
#define IMG    192
#define CCH    192
#define HIDN   768
#define NWIN   144
#define NHEAD  6
#define NTOK   256
#define KINN   128
#define TOPKN  64
#define QKVN   576

// ---------------- scratch buffers (static, no allocation) ----------------
__device__ __align__(128) float g_xn  [HW*CCH];
__device__ __align__(128) float g_sct [HW*CCH];
__device__ __align__(128) float g_qkv [HW*QKVN];
__device__ __align__(128) float g_vl  [HW*CCH];
__device__ __align__(128) float g_attn[HW*CCH];
__device__ __align__(128) float g_x2  [HW*CCH];
__device__ __align__(128) float g_yln [HW*CCH];
__device__ __align__(128) float g_yb  [HW*HIDN];
__device__ __align__(128) float g_y2  [HW*HIDN];
__device__ __align__(128) float g_wqkv[CCH*QKVN];
__device__ __align__(128) float g_bqkv[QKVN];
__device__ __align__(128) float g_wproj[CCH*CCH];
__device__ __align__(128) float g_wfc1 [CCH*HIDN];
__device__ __align__(128) float g_wfc2 [HIDN*CCH];

__device__ __forceinline__ float gelu_f(float x) {
    return 0.5f * x * (1.0f + erff(x * 0.70710678118654752f));
}

__device__ __forceinline__ float to_tf32(float x) {
    unsigned u;
    asm("cvt.rna.tf32.f32 %0, %1;" : "=r"(u) : "f"(x));
    return __uint_as_float(u);
}

__device__ __forceinline__ void mma_tf32(float* d, const unsigned* a, const unsigned* b) {
    asm volatile(
        "mma.sync.aligned.m16n8k8.row.col.f32.tf32.tf32.f32 "
        "{%0,%1,%2,%3}, {%4,%5,%6,%7}, {%8,%9}, {%0,%1,%2,%3};"
        : "+f"(d[0]), "+f"(d[1]), "+f"(d[2]), "+f"(d[3])
        : "r"(a[0]), "r"(a[1]), "r"(a[2]), "r"(a[3]), "r"(b[0]), "r"(b[1]));
}

__device__ __forceinline__ unsigned smem_u32(const void* p) {
    return (unsigned)__cvta_generic_to_shared(p);
}
__device__ __forceinline__ void cp16(unsigned dst, const void* src) {
    asm volatile("cp.async.cg.shared.global [%0], [%1], 16;\n" :: "r"(dst), "l"(src));
}
__device__ __forceinline__ void cp_commit() {
    asm volatile("cp.async.commit_group;\n");
}
template<int N>
__device__ __forceinline__ void cp_wait() {
    asm volatile("cp.async.wait_group %0;\n" :: "n"(N));
}

// ---------------- QKV weight/bias concat + tf32 round: [192][576] ------------
__global__ void qkv_prep_kernel(const float* __restrict__ wq, const float* __restrict__ wk,
                                const float* __restrict__ wv, const float* __restrict__ bq,
                                const float* __restrict__ bk, const float* __restrict__ bv,
                                float* __restrict__ w, float* __restrict__ b) {
    int idx = blockIdx.x * 256 + threadIdx.x;
    if (idx < CCH * QKVN) {
        int kk = idx / QKVN, n = idx % QKVN;
        float v;
        if (n < 192)      v = wq[kk * CCH + n];
        else if (n < 384) v = wk[kk * CCH + (n - 192)];
        else              v = wv[kk * CCH + (n - 384)];
        w[idx] = to_tf32(v);
    }
    if (idx < QKVN) {
        float v;
        if (idx < 192)      v = bq[idx];
        else if (idx < 384) v = bk[idx - 192];
        else                v = bv[idx - 384];
        b[idx] = v;
    }
}

// ---------------- tf32 round copy ----------------
__global__ void tf32_round_kernel(const float* __restrict__ src, float* __restrict__ dst,
                                  int n) {
    int idx = blockIdx.x * 256 + threadIdx.x;
    if (idx < n) dst[idx] = to_tf32(src[idx]);
}

// ---------------- LN1: transpose (C,HW)->(HW,C) + LayerNorm + raw transpose ---
#define LNP 48
__global__ void ln1_kernel(const float* __restrict__ f, const float* __restrict__ g,
                           const float* __restrict__ b, float* __restrict__ xn,
                           float* __restrict__ sct) {
    __shared__ float tile[LNP][193];
    __shared__ float mArr[LNP], rArr[LNP];
    const int t = threadIdx.x;
    const int p0 = blockIdx.x * LNP;
    for (int lin = t; lin < LNP * CCH; lin += 256) {
        int c = lin / LNP, p = lin % LNP;
        tile[p][c] = f[(size_t)c * HW + p0 + p];
    }
    __syncthreads();
    {
        int tq = t & 3, p = t >> 2;
        if (p < LNP) {
            float s = 0.f, s2 = 0.f;
            #pragma unroll 8
            for (int cc = 0; cc < 48; cc++) {
                float v = tile[p][tq * 48 + cc];
                s += v; s2 += v * v;
            }
            s  += __shfl_xor_sync(0xffffffffu, s, 1);
            s2 += __shfl_xor_sync(0xffffffffu, s2, 1);
            s  += __shfl_xor_sync(0xffffffffu, s, 2);
            s2 += __shfl_xor_sync(0xffffffffu, s2, 2);
            if (tq == 0) {
                float m = s * (1.f / CCH);
                float var = s2 * (1.f / CCH) - m * m;
                mArr[p] = m; rArr[p] = rsqrtf(var + 1e-5f);
            }
        }
    }
    __syncthreads();
    for (int lin = t; lin < LNP * CCH; lin += 256) {
        int p = lin / CCH, c = lin % CCH;
        float v = tile[p][c];
        size_t o = (size_t)(p0 + p) * CCH + c;
        sct[o] = v;
        xn[o] = (v - mArr[p]) * rArr[p] * g[c] + b[c];
    }
}

// ---------------- LN2: row-major (HW,C) LayerNorm, float4 ----------------
__global__ void ln2_kernel(const float* __restrict__ x, const float* __restrict__ g,
                           const float* __restrict__ b, float* __restrict__ y) {
    int p = blockIdx.x * 256 + threadIdx.x;
    const float4* row = (const float4*)(x + (size_t)p * CCH);
    float s = 0.f, s2 = 0.f;
    #pragma unroll
    for (int c = 0; c < CCH / 4; c++) {
        float4 v = row[c];
        s += v.x + v.y + v.z + v.w;
        s2 += v.x * v.x + v.y * v.y + v.z * v.z + v.w * v.w;
    }
    float m = s * (1.f / CCH);
    float var = s2 * (1.f / CCH) - m * m;
    float r = rsqrtf(var + 1e-5f);
    const float4* g4 = (const float4*)g;
    const float4* b4 = (const float4*)b;
    float4* orow = (float4*)(y + (size_t)p * CCH);
    #pragma unroll
    for (int c = 0; c < CCH / 4; c++) {
        float4 v = row[c], gg = g4[c], bb = b4[c], o;
        o.x = (v.x - m) * r * gg.x + bb.x;
        o.y = (v.y - m) * r * gg.y + bb.y;
        o.z = (v.z - m) * r * gg.z + bb.z;
        o.w = (v.w - m) * r * gg.w + bb.w;
        orow[c] = o;
    }
}

// ---- TGEMM v5 (tf32 mma): BM=64, BN=192, BK=16, 128 thr (4 warps 2x2),
//      B via 3-stage cp.async (pre-rounded tf32 weights),
//      A via register prefetch + cvt.rna + STS -> [k][m] stride 72 ----
#define A_ROW   72
#define A_BUF   (16 * A_ROW)
#define BS_STRIDE 200
#define B_STAGE (16 * BS_STRIDE)
#define GEMM_SMEM_BYTES ((2 * A_BUF + 3 * B_STAGE) * 4)

template<int ACT, int RES>
__global__ void __launch_bounds__(128, 3)
tgemm_kernel(const float* __restrict__ A, const float* __restrict__ B,
             const float* __restrict__ bias, float* __restrict__ C,
             int M, int N, int K, const float* __restrict__ res) {
    extern __shared__ float sm[];
    float* As = sm;
    float* Bs = sm + 2 * A_BUF;
    const int tid = threadIdx.x;
    const int m0 = blockIdx.y * 64, n0 = blockIdx.x * 192;
    const int warp = tid >> 5, lane = tid & 31;
    const int g = lane >> 2, r4 = lane & 3;
    const int wm = warp & 1, wn = warp >> 1;

    // A staging mapping
    const int am = tid >> 1, ak = (tid & 1) * 8;
    const float* Asrc = A + (size_t)(m0 + am) * K + ak;
    // B cp.async mapping: 6 chunks
    int bkc[6], bnc[6];
    #pragma unroll
    for (int j = 0; j < 6; j++) {
        int lin = tid + j * 128;
        bkc[j] = lin / 48; bnc[j] = (lin % 48) * 4;
    }

    const int nT = K >> 4;

    auto issueB = [&](int slot, int kt) {
        if (kt < nT) {
            float* bs = Bs + slot * B_STAGE;
            #pragma unroll
            for (int j = 0; j < 6; j++) {
                unsigned db = smem_u32(bs + bkc[j] * BS_STRIDE + bnc[j]);
                cp16(db, B + (size_t)(kt * 16 + bkc[j]) * N + n0 + bnc[j]);
            }
        }
        cp_commit();
    };

    float acc[2][12][4];
    #pragma unroll
    for (int i = 0; i < 2; i++)
        #pragma unroll
        for (int j = 0; j < 12; j++)
            #pragma unroll
            for (int e = 0; e < 4; e++) acc[i][j][e] = 0.f;

    // prologue
    float4 a0 = *(const float4*)(Asrc);
    float4 a1 = *(const float4*)(Asrc + 4);
    {
        float* as = As;
        as[(ak + 0) * A_ROW + am] = to_tf32(a0.x);
        as[(ak + 1) * A_ROW + am] = to_tf32(a0.y);
        as[(ak + 2) * A_ROW + am] = to_tf32(a0.z);
        as[(ak + 3) * A_ROW + am] = to_tf32(a0.w);
        as[(ak + 4) * A_ROW + am] = to_tf32(a1.x);
        as[(ak + 5) * A_ROW + am] = to_tf32(a1.y);
        as[(ak + 6) * A_ROW + am] = to_tf32(a1.z);
        as[(ak + 7) * A_ROW + am] = to_tf32(a1.w);
    }
    issueB(0, 0);
    issueB(1, 1);
    cp_wait<1>();
    __syncthreads();

    for (int t = 0; t < nT; t++) {
        if (t + 1 < nT) {
            a0 = *(const float4*)(Asrc + (size_t)(t + 1) * 16);
            a1 = *(const float4*)(Asrc + (size_t)(t + 1) * 16 + 4);
        }
        const float* as = As + (t & 1) * A_BUF;
        const float* bs = Bs + (t % 3) * B_STAGE;
        #pragma unroll
        for (int s = 0; s < 2; s++) {
            const int ks = s * 8;
            unsigned bfr[12][2];
            #pragma unroll
            for (int nf = 0; nf < 12; nf++) {
                int nb = wn * 96 + nf * 8 + g;
                bfr[nf][0] = __float_as_uint(bs[(ks + r4) * BS_STRIDE + nb]);
                bfr[nf][1] = __float_as_uint(bs[(ks + r4 + 4) * BS_STRIDE + nb]);
            }
            #pragma unroll
            for (int mf = 0; mf < 2; mf++) {
                int mb = wm * 32 + mf * 16 + g;
                unsigned af[4];
                af[0] = __float_as_uint(as[(ks + r4) * A_ROW + mb]);
                af[1] = __float_as_uint(as[(ks + r4) * A_ROW + mb + 8]);
                af[2] = __float_as_uint(as[(ks + r4 + 4) * A_ROW + mb]);
                af[3] = __float_as_uint(as[(ks + r4 + 4) * A_ROW + mb + 8]);
                #pragma unroll
                for (int nf = 0; nf < 12; nf++)
                    mma_tf32(acc[mf][nf], af, bfr[nf]);
            }
        }
        issueB((t + 2) % 3, t + 2);
        if (t + 1 < nT) {
            float* as2 = As + ((t + 1) & 1) * A_BUF;
            as2[(ak + 0) * A_ROW + am] = to_tf32(a0.x);
            as2[(ak + 1) * A_ROW + am] = to_tf32(a0.y);
            as2[(ak + 2) * A_ROW + am] = to_tf32(a0.z);
            as2[(ak + 3) * A_ROW + am] = to_tf32(a0.w);
            as2[(ak + 4) * A_ROW + am] = to_tf32(a1.x);
            as2[(ak + 5) * A_ROW + am] = to_tf32(a1.y);
            as2[(ak + 6) * A_ROW + am] = to_tf32(a1.z);
            as2[(ak + 7) * A_ROW + am] = to_tf32(a1.w);
        }
        cp_wait<1>();
        __syncthreads();
    }

    // epilogue: fragment (mf,nf): rows m0+wm*32+mf*16+g (+8), cols n0+wn*96+nf*8+2*r4 (+1)
    #pragma unroll
    for (int mf = 0; mf < 2; mf++) {
        #pragma unroll
        for (int nf = 0; nf < 12; nf++) {
            int mrow = m0 + wm * 32 + mf * 16 + g;
            int ncol = n0 + wn * 96 + nf * 8 + 2 * r4;
            float bx = bias[ncol], by = bias[ncol + 1];
            #pragma unroll
            for (int half = 0; half < 2; half++) {
                int m = mrow + half * 8;
                float ox = acc[mf][nf][half * 2 + 0] + bx;
                float oy = acc[mf][nf][half * 2 + 1] + by;
                if (ACT == 1) { ox = gelu_f(ox); oy = gelu_f(oy); }
                if (RES == 1) {
                    float2 rv = *(const float2*)(res + (size_t)m * N + ncol);
                    ox += rv.x; oy += rv.y;
                }
                float2 o = make_float2(ox, oy);
                *(float2*)(C + (size_t)m * N + ncol) = o;
            }
        }
    }
}

// ---------------- dwconv: smem tile 8x8 px x 16 ch, 12x12 halo ----------------
__global__ void dwconv_kernel(const float* __restrict__ in, int instride,
                              const float* __restrict__ wgt,
                              const float* __restrict__ bias, float* __restrict__ out,
                              int Cn, int addin) {
    __shared__ float4 tile[12 * 12 * 4];
    __shared__ float wsm[16][26];
    const int tid = threadIdx.x;
    const int c4l = tid & 3, px = (tid >> 2) & 7, py = tid >> 5;
    const int c4b = blockIdx.y;
    const int gx0 = (blockIdx.x % 24) * 8, gy0 = (blockIdx.x / 24) * 8;

    for (int lw = tid; lw < 400; lw += 256)
        wsm[lw / 25][lw % 25] = wgt[(c4b * 16 + lw / 25) * 25 + lw % 25];

    for (int lin = tid; lin < 576; lin += 256) {
        int cc = lin & 3, rem = lin >> 2;
        int xx = rem % 12, yy = rem / 12;
        int gy = gy0 + yy - 2, gx = gx0 + xx - 2;
        float4 v = make_float4(0.f, 0.f, 0.f, 0.f);
        if ((unsigned)gy < (unsigned)IMG && (unsigned)gx < (unsigned)IMG)
            v = *(const float4*)(in + (size_t)(gy * IMG + gx) * instride + (c4b * 4 + cc) * 4);
        tile[(yy * 12 + xx) * 4 + cc] = v;
    }
    __syncthreads();

    float4 a = *(const float4*)(bias + (c4b * 4 + c4l) * 4);
    #pragma unroll
    for (int ky = 0; ky < 5; ky++) {
        #pragma unroll
        for (int kx = 0; kx < 5; kx++) {
            float4 v = tile[((py + ky) * 12 + px + kx) * 4 + c4l];
            int tp = ky * 5 + kx;
            a.x += v.x * wsm[c4l * 4 + 0][tp];
            a.y += v.y * wsm[c4l * 4 + 1][tp];
            a.z += v.z * wsm[c4l * 4 + 2][tp];
            a.w += v.w * wsm[c4l * 4 + 3][tp];
        }
    }
    float4 o;
    o.x = gelu_f(a.x); o.y = gelu_f(a.y); o.z = gelu_f(a.z); o.w = gelu_f(a.w);
    if (addin) {
        float4 iv = tile[((py + 2) * 12 + px + 2) * 4 + c4l];
        o.x += iv.x; o.y += iv.y; o.z += iv.z; o.w += iv.w;
    }
    *(float4*)(out + (size_t)((gy0 + py) * IMG + gx0 + px) * Cn + (c4b * 4 + c4l) * 4) = o;
}

// ---------------- attention v3: fp16 K/V smem, merged softmax/prior ----------
#define KHS 258
#define ATTN_SMEM_BYTES (2*16*KHS*4 + 128*256*4 + 128*260)
__global__ void attn_kernel(const float* __restrict__ qkv, const float* __restrict__ vl,
                            const float* __restrict__ pfa_v, const int* __restrict__ pfa_i,
                            const int* __restrict__ rpi, const float* __restrict__ rpb,
                            float* __restrict__ out) {
    extern __shared__ char smA[];
    __half2* kh = (__half2*)smA;                           // [p][j], stride KHS
    __half2* vh = kh + 16 * KHS;
    float* sc = (float*)(vh + 16 * KHS);                   // [kk][t]
    unsigned char* js = (unsigned char*)(sc + 128 * 256);  // [kk][260]

    const int t = threadIdx.x;
    const int h = blockIdx.x;
    const int w = blockIdx.y;
    const int wy = w / 12, wx = w % 12;
    const size_t whbase = ((size_t)w * NHEAD + h) * NTOK;

    const float* qg = qkv;
    const float* kg = qkv + 192;
    const float* vg = qkv + 384;

    #pragma unroll
    for (int rb = 0; rb < 256; rb += 32) {
        int r = rb + (t >> 3), e = t & 7;
        int pj = (wy * 16 + (r >> 4)) * IMG + wx * 16 + (r & 15);
        float4 kvl = *(const float4*)(kg + (size_t)pj * QKVN + h * 32 + e * 4);
        kh[(2 * e + 0) * KHS + r] = __floats2half2_rn(kvl.x, kvl.y);
        kh[(2 * e + 1) * KHS + r] = __floats2half2_rn(kvl.z, kvl.w);
        float4 vv4 = *(const float4*)(vg + (size_t)pj * QKVN + h * 32 + e * 4);
        vh[(2 * e + 0) * KHS + r] = __floats2half2_rn(vv4.x, vv4.y);
        vh[(2 * e + 1) * KHS + r] = __floats2half2_rn(vv4.z, vv4.w);
    }
    {
        const int* idxg = pfa_i + whbase * KINN;
        for (int e = t; e < NTOK * KINN; e += 256)
            js[(e & 127) * 260 + (e >> 7)] = (unsigned char)idxg[e];
    }
    __syncthreads();

    const int i = t;
    const int pi = (wy * 16 + (i >> 4)) * IMG + wx * 16 + (i & 15);

    float qreg[32];
    {
        const float4* qr = (const float4*)(qg + (size_t)pi * QKVN + h * 32);
        const float scl = 0.17677669529663688f;  // 1/sqrt(32)
        #pragma unroll
        for (int e = 0; e < 8; e++) {
            float4 a4 = qr[e];
            qreg[e * 4 + 0] = a4.x * scl; qreg[e * 4 + 1] = a4.y * scl;
            qreg[e * 4 + 2] = a4.z * scl; qreg[e * 4 + 3] = a4.w * scl;
        }
    }

    const int* rr = rpi + i * NTOK;
    float mx = -1e30f;
    #pragma unroll 2
    for (int kk = 0; kk < KINN; kk++) {
        int j = js[kk * 260 + t];
        float d = 0.f;
        #pragma unroll
        for (int p = 0; p < 16; p++) {
            float2 f = __half22float2(kh[p * KHS + j]);
            d += qreg[2 * p] * f.x + qreg[2 * p + 1] * f.y;
        }
        d += __ldg(&rpb[__ldg(&rr[j]) * NHEAD + h]);
        sc[kk * 256 + t] = d;
        mx = fmaxf(mx, d);
    }

    const float* pv = pfa_v + (whbase + i) * KINN;
    float sE = 0.f, sU = 0.f;
    float gmax[16];
    #pragma unroll
    for (int g = 0; g < 16; g++) {
        float gm = -3.f;
        #pragma unroll
        for (int e2 = 0; e2 < 8; e2 += 4) {
            int kk = g * 8 + e2;
            float4 p4 = *(const float4*)(pv + kk);
            float e0 = __expf(sc[(kk + 0) * 256 + t] - mx);
            float e1 = __expf(sc[(kk + 1) * 256 + t] - mx);
            float e2f = __expf(sc[(kk + 2) * 256 + t] - mx);
            float e3 = __expf(sc[(kk + 3) * 256 + t] - mx);
            sE += e0 + e1 + e2f + e3;
            float u0 = e0 * p4.x, u1 = e1 * p4.y, u2 = e2f * p4.z, u3 = e3 * p4.w;
            sc[(kk + 0) * 256 + t] = u0; sc[(kk + 1) * 256 + t] = u1;
            sc[(kk + 2) * 256 + t] = u2; sc[(kk + 3) * 256 + t] = u3;
            sU += u0 + u1 + u2 + u3;
            gm = fmaxf(gm, fmaxf(fmaxf(u0, u1), fmaxf(u2, u3)));
        }
        gmax[g] = gm;
    }
    const float epsE = 1e-10f * sE;
    const float r2 = 1.0f / (sU + epsE);

    float acc[32];
    #pragma unroll
    for (int dd = 0; dd < 32; dd++) acc[dd] = 0.f;
    for (int sel = 0; sel < TOPKN; sel++) {
        float best = gmax[0]; int bg = 0;
        #pragma unroll
        for (int g = 1; g < 16; g++)
            if (gmax[g] > best) { best = gmax[g]; bg = g; }
        float m1 = -3.f, m2 = -3.f; int be = 0;
        #pragma unroll
        for (int e2 = 0; e2 < 8; e2++) {
            float vv = sc[(bg * 8 + e2) * 256 + t];
            if (vv > m1) { m2 = m1; m1 = vv; be = e2; }
            else m2 = fmaxf(m2, vv);
        }
        int bkk = bg * 8 + be;
        sc[bkk * 256 + t] = -3.f;
        #pragma unroll
        for (int g = 0; g < 16; g++) if (g == bg) gmax[g] = m2;

        int j = js[bkk * 260 + t];
        float wv = (m1 + epsE) * r2;
        #pragma unroll
        for (int p = 0; p < 16; p++) {
            float2 f = __half22float2(vh[p * KHS + j]);
            acc[2 * p] += wv * f.x;
            acc[2 * p + 1] += wv * f.y;
        }
    }

    float* op = out + (size_t)pi * CCH + h * 32;
    const float* vp = vl + (size_t)pi * CCH + h * 32;
    #pragma unroll
    for (int e = 0; e < 8; e++) {
        float4 o;
        o.x = acc[e * 4 + 0] + vp[e * 4 + 0];
        o.y = acc[e * 4 + 1] + vp[e * 4 + 1];
        o.z = acc[e * 4 + 2] + vp[e * 4 + 2];
        o.w = acc[e * 4 + 3] + vp[e * 4 + 3];
        *(float4*)(op + e * 4) = o;
    }
}

// ---------------- launch ----------------
extern "C" void kernel_launch(void* const* d_in, const int* in_sizes, int n_in,
                              void* d_out, int out_size) {
    const float* features = (const float*)d_in[0];
    const float* pfa_v    = (const float*)d_in[1];
    const int*   pfa_i    = (const int*)  d_in[2];
    const int*   rpi      = (const int*)  d_in[3];
    const float* ln1_g    = (const float*)d_in[4];
    const float* ln1_b    = (const float*)d_in[5];
    const float* Wq_w     = (const float*)d_in[6];
    const float* Wq_b     = (const float*)d_in[7];
    const float* Wk_w     = (const float*)d_in[8];
    const float* Wk_b     = (const float*)d_in[9];
    const float* Wv_w     = (const float*)d_in[10];
    const float* Wv_b     = (const float*)d_in[11];
    const float* lepe_w   = (const float*)d_in[12];
    const float* lepe_b   = (const float*)d_in[13];
    const float* rpb_tab  = (const float*)d_in[14];
    const float* proj_w   = (const float*)d_in[15];
    const float* proj_b   = (const float*)d_in[16];
    const float* ln2_g    = (const float*)d_in[17];
    const float* ln2_b    = (const float*)d_in[18];
    const float* fc1_w    = (const float*)d_in[19];
    const float* fc1_b    = (const float*)d_in[20];
    const float* ffn_dw_w = (const float*)d_in[21];
    const float* ffn_dw_b = (const float*)d_in[22];
    const float* fc2_w    = (const float*)d_in[23];
    const float* fc2_b    = (const float*)d_in[24];
    float* outp = (float*)d_out;

    float *xn, *sct, *qkvb, *vlb, *attnb, *x2b, *ylnb, *ybb, *y2b;
    float *wqkv, *bqkv, *wproj, *wfc1, *wfc2;
    cudaGetSymbolAddress((void**)&xn,    g_xn);
    cudaGetSymbolAddress((void**)&sct,   g_sct);
    cudaGetSymbolAddress((void**)&qkvb,  g_qkv);
    cudaGetSymbolAddress((void**)&vlb,   g_vl);
    cudaGetSymbolAddress((void**)&attnb, g_attn);
    cudaGetSymbolAddress((void**)&x2b,   g_x2);
    cudaGetSymbolAddress((void**)&ylnb,  g_yln);
    cudaGetSymbolAddress((void**)&ybb,   g_yb);
    cudaGetSymbolAddress((void**)&y2b,   g_y2);
    cudaGetSymbolAddress((void**)&wqkv,  g_wqkv);
    cudaGetSymbolAddress((void**)&bqkv,  g_bqkv);
    cudaGetSymbolAddress((void**)&wproj, g_wproj);
    cudaGetSymbolAddress((void**)&wfc1,  g_wfc1);
    cudaGetSymbolAddress((void**)&wfc2,  g_wfc2);

    cudaFuncSetAttribute(attn_kernel, cudaFuncAttributeMaxDynamicSharedMemorySize,
                         ATTN_SMEM_BYTES);
    cudaFuncSetAttribute(tgemm_kernel<0, 0>, cudaFuncAttributeMaxDynamicSharedMemorySize,
                         GEMM_SMEM_BYTES);
    cudaFuncSetAttribute(tgemm_kernel<0, 1>, cudaFuncAttributeMaxDynamicSharedMemorySize,
                         GEMM_SMEM_BYTES);
    cudaFuncSetAttribute(tgemm_kernel<1, 0>, cudaFuncAttributeMaxDynamicSharedMemorySize,
                         GEMM_SMEM_BYTES);

    const int M = HW;

    // 0) weight prep: concat+round QKV; round proj/fc1/fc2 to tf32
    qkv_prep_kernel<<<(CCH * QKVN + 255) / 256, 256>>>(Wq_w, Wk_w, Wv_w,
                                                       Wq_b, Wk_b, Wv_b, wqkv, bqkv);
    tf32_round_kernel<<<(CCH * CCH + 255) / 256, 256>>>(proj_w, wproj, CCH * CCH);
    tf32_round_kernel<<<(CCH * HIDN + 255) / 256, 256>>>(fc1_w, wfc1, CCH * HIDN);
    tf32_round_kernel<<<(HIDN * CCH + 255) / 256, 256>>>(fc2_w, wfc2, HIDN * CCH);

    // 1) transpose + LN1 (+ raw transposed shortcut)
    ln1_kernel<<<HW / LNP, 256>>>(features, ln1_g, ln1_b, xn, sct);

    // 2) fused QKV projection: (HW,192) @ (192,576)
    tgemm_kernel<0, 0><<<dim3(3, M / 64), 128, GEMM_SMEM_BYTES>>>(
        xn, wqkv, bqkv, qkvb, M, QKVN, CCH, nullptr);

    // 3) LePE: depthwise 5x5 + GELU on V slice of qkv
    dwconv_kernel<<<dim3(576, CCH / 16), 256>>>(qkvb + 384, QKVN, lepe_w, lepe_b,
                                                vlb, CCH, 0);

    // 4) sparse windowed attention (+vl)
    attn_kernel<<<dim3(NHEAD, NWIN), 256, ATTN_SMEM_BYTES>>>(
        qkvb, vlb, pfa_v, pfa_i, rpi, rpb_tab, attnb);

    // 5) output projection + shortcut (coalesced transposed residual)
    dim3 g192(1, M / 64);
    tgemm_kernel<0, 1><<<g192, 128, GEMM_SMEM_BYTES>>>(attnb, wproj, proj_b, x2b,
                                                       M, CCH, CCH, sct);

    // 6) ConvFFN
    ln2_kernel<<<HW / 256, 256>>>(x2b, ln2_g, ln2_b, ylnb);
    tgemm_kernel<1, 0><<<dim3(4, M / 64), 128, GEMM_SMEM_BYTES>>>(
        ylnb, wfc1, fc1_b, ybb, M, HIDN, CCH, nullptr);
    dwconv_kernel<<<dim3(576, HIDN / 16), 256>>>(ybb, HIDN, ffn_dw_w, ffn_dw_b,
                                                 y2b, HIDN, 1);
    tgemm_kernel<0, 1><<<g192, 128, GEMM_SMEM_BYTES>>>(y2b, wfc2, fc2_b, outp,
                                                       M, CCH, HIDN, x2b);
    (void)in_sizes; (void)n_in; (void)out_size;
}

// round 17
// speedup vs baseline: 1.5380x; 1.0456x over previous
#include <cuda_runtime.h>
#include <cuda_bf16.h>
#include <cuda_fp16.h>
#include <math.h>

#define HW     36864
#define IMG    192
#define CCH    192
#define HIDN   768
#define NWIN   144
#define NHEAD  6
#define NTOK   256
#define KINN   128
#define TOPKN  64
#define QKVN   576

// ---------------- scratch buffers (static, no allocation) ----------------
__device__ __align__(128) float g_xn  [HW*CCH];
__device__ __align__(128) float g_sct [HW*CCH];
__device__ __align__(128) float g_qkv [HW*QKVN];
__device__ __align__(128) float g_vl  [HW*CCH];
__device__ __align__(128) float g_attn[HW*CCH];
__device__ __align__(128) float g_x2  [HW*CCH];
__device__ __align__(128) float g_yln [HW*CCH];
__device__ __align__(128) float g_yb  [HW*HIDN];
__device__ __align__(128) float g_y2  [HW*HIDN];
// packed half2 weights: [K/2][N], word = (W[2kp][n] low, W[2kp+1][n] high)
__device__ __align__(128) unsigned g_wqkvh[(CCH/2)*QKVN];
__device__ __align__(128) unsigned g_wprojh[(CCH/2)*CCH];
__device__ __align__(128) unsigned g_wfc1h [(CCH/2)*HIDN];
__device__ __align__(128) unsigned g_wfc2h [(HIDN/2)*CCH];
__device__ __align__(128) float g_bqkv[QKVN];

__device__ __forceinline__ float gelu_f(float x) {
    return 0.5f * x * (1.0f + erff(x * 0.70710678118654752f));
}

__device__ __forceinline__ unsigned packh2(float a, float b) {
    __half2 h = __floats2half2_rn(a, b);
    return *(unsigned*)&h;
}

__device__ __forceinline__ void mma_fp16(float* d, const unsigned* a, const unsigned* b) {
    asm volatile(
        "mma.sync.aligned.m16n8k16.row.col.f32.f16.f16.f32 "
        "{%0,%1,%2,%3}, {%4,%5,%6,%7}, {%8,%9}, {%0,%1,%2,%3};"
        : "+f"(d[0]), "+f"(d[1]), "+f"(d[2]), "+f"(d[3])
        : "r"(a[0]), "r"(a[1]), "r"(a[2]), "r"(a[3]), "r"(b[0]), "r"(b[1]));
}

__device__ __forceinline__ unsigned smem_u32(const void* p) {
    return (unsigned)__cvta_generic_to_shared(p);
}
__device__ __forceinline__ void cp16(unsigned dst, const void* src) {
    asm volatile("cp.async.cg.shared.global [%0], [%1], 16;\n" :: "r"(dst), "l"(src));
}
__device__ __forceinline__ void cp_commit() {
    asm volatile("cp.async.commit_group;\n");
}
template<int N>
__device__ __forceinline__ void cp_wait() {
    asm volatile("cp.async.wait_group %0;\n" :: "n"(N));
}

// ------------- QKV prep: concat + pack half2 [96][576]; bias concat ---------
__global__ void qkv_prep_kernel(const float* __restrict__ wq, const float* __restrict__ wk,
                                const float* __restrict__ wv, const float* __restrict__ bq,
                                const float* __restrict__ bk, const float* __restrict__ bv,
                                unsigned* __restrict__ w, float* __restrict__ b) {
    int idx = blockIdx.x * 256 + threadIdx.x;
    if (idx < (CCH / 2) * QKVN) {
        int kp = idx / QKVN, n = idx % QKVN;
        const float* src; int nc;
        if (n < 192)      { src = wq; nc = n; }
        else if (n < 384) { src = wk; nc = n - 192; }
        else              { src = wv; nc = n - 384; }
        w[idx] = packh2(src[(2 * kp) * CCH + nc], src[(2 * kp + 1) * CCH + nc]);
    }
    if (idx < QKVN) {
        float v;
        if (idx < 192)      v = bq[idx];
        else if (idx < 384) v = bk[idx - 192];
        else                v = bv[idx - 384];
        b[idx] = v;
    }
}

// ------------- generic pack: src f32 [2*K2][N] -> dst u32 [K2][N] -----------
__global__ void pack_half_kernel(const float* __restrict__ src, unsigned* __restrict__ dst,
                                 int K2, int N) {
    int idx = blockIdx.x * 256 + threadIdx.x;
    if (idx < K2 * N) {
        int kp = idx / N, n = idx % N;
        dst[idx] = packh2(src[(2 * kp) * N + n], src[(2 * kp + 1) * N + n]);
    }
}

// ---------------- LN1: transpose (C,HW)->(HW,C) + LayerNorm + raw transpose ---
#define LNP 48
__global__ void ln1_kernel(const float* __restrict__ f, const float* __restrict__ g,
                           const float* __restrict__ b, float* __restrict__ xn,
                           float* __restrict__ sct) {
    __shared__ float tile[LNP][193];
    __shared__ float mArr[LNP], rArr[LNP];
    const int t = threadIdx.x;
    const int p0 = blockIdx.x * LNP;
    for (int lin = t; lin < LNP * CCH; lin += 256) {
        int c = lin / LNP, p = lin % LNP;
        tile[p][c] = f[(size_t)c * HW + p0 + p];
    }
    __syncthreads();
    {
        int tq = t & 3, p = t >> 2;
        if (p < LNP) {
            float s = 0.f, s2 = 0.f;
            #pragma unroll 8
            for (int cc = 0; cc < 48; cc++) {
                float v = tile[p][tq * 48 + cc];
                s += v; s2 += v * v;
            }
            s  += __shfl_xor_sync(0xffffffffu, s, 1);
            s2 += __shfl_xor_sync(0xffffffffu, s2, 1);
            s  += __shfl_xor_sync(0xffffffffu, s, 2);
            s2 += __shfl_xor_sync(0xffffffffu, s2, 2);
            if (tq == 0) {
                float m = s * (1.f / CCH);
                float var = s2 * (1.f / CCH) - m * m;
                mArr[p] = m; rArr[p] = rsqrtf(var + 1e-5f);
            }
        }
    }
    __syncthreads();
    for (int lin = t; lin < LNP * CCH; lin += 256) {
        int p = lin / CCH, c = lin % CCH;
        float v = tile[p][c];
        size_t o = (size_t)(p0 + p) * CCH + c;
        sct[o] = v;
        xn[o] = (v - mArr[p]) * rArr[p] * g[c] + b[c];
    }
}

// ---------------- LN2: row-major (HW,C) LayerNorm, float4 ----------------
__global__ void ln2_kernel(const float* __restrict__ x, const float* __restrict__ g,
                           const float* __restrict__ b, float* __restrict__ y) {
    int p = blockIdx.x * 256 + threadIdx.x;
    const float4* row = (const float4*)(x + (size_t)p * CCH);
    float s = 0.f, s2 = 0.f;
    #pragma unroll
    for (int c = 0; c < CCH / 4; c++) {
        float4 v = row[c];
        s += v.x + v.y + v.z + v.w;
        s2 += v.x * v.x + v.y * v.y + v.z * v.z + v.w * v.w;
    }
    float m = s * (1.f / CCH);
    float var = s2 * (1.f / CCH) - m * m;
    float r = rsqrtf(var + 1e-5f);
    const float4* g4 = (const float4*)g;
    const float4* b4 = (const float4*)b;
    float4* orow = (float4*)(y + (size_t)p * CCH);
    #pragma unroll
    for (int c = 0; c < CCH / 4; c++) {
        float4 v = row[c], gg = g4[c], bb = b4[c], o;
        o.x = (v.x - m) * r * gg.x + bb.x;
        o.y = (v.y - m) * r * gg.y + bb.y;
        o.z = (v.z - m) * r * gg.z + bb.z;
        o.w = (v.w - m) * r * gg.w + bb.w;
        orow[c] = o;
    }
}

// ---- HGEMM v6 (fp16 mma m16n8k16): BM=64, BN=192, BK=16, 128 thr (2x2 warps)
//      B: pre-packed half2 words via 3-stage cp.async; A: f32 load + cvt + STS.
//      smem u32 layouts: A [kp][m] stride 72; B [kp][n] stride 200. ----
#define AROW32  72
#define A_BUF32 (8 * AROW32)            // 576 u32 per buffer
#define BROW32  200
#define B_STAGE32 (8 * BROW32)          // 1600 u32 per stage
#define GEMM_SMEM_BYTES ((2 * A_BUF32 + 3 * B_STAGE32) * 4)

template<int ACT, int RES>
__global__ void __launch_bounds__(128, 3)
hgemm_kernel(const float* __restrict__ A, const unsigned* __restrict__ B,
             const float* __restrict__ bias, float* __restrict__ C,
             int M, int N, int K, const float* __restrict__ res) {
    extern __shared__ unsigned smu[];
    unsigned* As = smu;
    unsigned* Bs = smu + 2 * A_BUF32;
    const int tid = threadIdx.x;
    const int m0 = blockIdx.y * 64, n0 = blockIdx.x * 192;
    const int warp = tid >> 5, lane = tid & 31;
    const int g = lane >> 2, r4 = lane & 3;
    const int wm = warp & 1, wn = warp >> 1;

    // A staging: thread covers row am, k [ak, ak+8) -> 4 packed words kp0..kp0+3
    const int am = tid >> 1, ak = (tid & 1) * 8, kp0 = (tid & 1) * 4;
    const float* Asrc = A + (size_t)(m0 + am) * K + ak;
    // B cp.async: stage = 8 rows x 192 u32 = 384 chunks of 16B; 3 per thread
    int bkc[3], bnc[3];
    #pragma unroll
    for (int j = 0; j < 3; j++) {
        int lin = tid + j * 128;
        bkc[j] = lin / 48; bnc[j] = (lin % 48) * 4;   // u32 index
    }

    const int nT = K >> 4;
    const int Np2 = N;                  // packed row length in u32 = N

    auto issueB = [&](int slot, int kt) {
        if (kt < nT) {
            unsigned* bs = Bs + slot * B_STAGE32;
            #pragma unroll
            for (int j = 0; j < 3; j++) {
                unsigned db = smem_u32(bs + bkc[j] * BROW32 + bnc[j]);
                cp16(db, B + (size_t)(kt * 8 + bkc[j]) * Np2 + n0 + bnc[j]);
            }
        }
        cp_commit();
    };

    float acc[2][12][4];
    #pragma unroll
    for (int i = 0; i < 2; i++)
        #pragma unroll
        for (int j = 0; j < 12; j++)
            #pragma unroll
            for (int e = 0; e < 4; e++) acc[i][j][e] = 0.f;

    // prologue
    float4 a0 = *(const float4*)(Asrc);
    float4 a1 = *(const float4*)(Asrc + 4);
    {
        unsigned* as = As;
        as[(kp0 + 0) * AROW32 + am] = packh2(a0.x, a0.y);
        as[(kp0 + 1) * AROW32 + am] = packh2(a0.z, a0.w);
        as[(kp0 + 2) * AROW32 + am] = packh2(a1.x, a1.y);
        as[(kp0 + 3) * AROW32 + am] = packh2(a1.z, a1.w);
    }
    issueB(0, 0);
    issueB(1, 1);
    cp_wait<1>();
    __syncthreads();

    for (int t = 0; t < nT; t++) {
        if (t + 1 < nT) {
            a0 = *(const float4*)(Asrc + (size_t)(t + 1) * 16);
            a1 = *(const float4*)(Asrc + (size_t)(t + 1) * 16 + 4);
        }
        const unsigned* as = As + (t & 1) * A_BUF32;
        const unsigned* bs = Bs + (t % 3) * B_STAGE32;
        {
            unsigned bfr[12][2];
            #pragma unroll
            for (int nf = 0; nf < 12; nf++) {
                int nb = wn * 96 + nf * 8 + g;
                bfr[nf][0] = bs[r4 * BROW32 + nb];
                bfr[nf][1] = bs[(r4 + 4) * BROW32 + nb];
            }
            #pragma unroll
            for (int mf = 0; mf < 2; mf++) {
                int mb = wm * 32 + mf * 16 + g;
                unsigned af[4];
                af[0] = as[r4 * AROW32 + mb];
                af[1] = as[r4 * AROW32 + mb + 8];
                af[2] = as[(r4 + 4) * AROW32 + mb];
                af[3] = as[(r4 + 4) * AROW32 + mb + 8];
                #pragma unroll
                for (int nf = 0; nf < 12; nf++)
                    mma_fp16(acc[mf][nf], af, bfr[nf]);
            }
        }
        issueB((t + 2) % 3, t + 2);
        if (t + 1 < nT) {
            unsigned* as2 = As + ((t + 1) & 1) * A_BUF32;
            as2[(kp0 + 0) * AROW32 + am] = packh2(a0.x, a0.y);
            as2[(kp0 + 1) * AROW32 + am] = packh2(a0.z, a0.w);
            as2[(kp0 + 2) * AROW32 + am] = packh2(a1.x, a1.y);
            as2[(kp0 + 3) * AROW32 + am] = packh2(a1.z, a1.w);
        }
        cp_wait<1>();
        __syncthreads();
    }

    // epilogue: fragment (mf,nf): rows m0+wm*32+mf*16+g (+8), cols n0+wn*96+nf*8+2*r4 (+1)
    #pragma unroll
    for (int mf = 0; mf < 2; mf++) {
        #pragma unroll
        for (int nf = 0; nf < 12; nf++) {
            int mrow = m0 + wm * 32 + mf * 16 + g;
            int ncol = n0 + wn * 96 + nf * 8 + 2 * r4;
            float bx = bias[ncol], by = bias[ncol + 1];
            #pragma unroll
            for (int half = 0; half < 2; half++) {
                int m = mrow + half * 8;
                float ox = acc[mf][nf][half * 2 + 0] + bx;
                float oy = acc[mf][nf][half * 2 + 1] + by;
                if (ACT == 1) { ox = gelu_f(ox); oy = gelu_f(oy); }
                if (RES == 1) {
                    float2 rv = *(const float2*)(res + (size_t)m * N + ncol);
                    ox += rv.x; oy += rv.y;
                }
                float2 o = make_float2(ox, oy);
                *(float2*)(C + (size_t)m * N + ncol) = o;
            }
        }
    }
}

// ---------------- dwconv: smem tile 8x8 px x 16 ch, 12x12 halo ----------------
__global__ void dwconv_kernel(const float* __restrict__ in, int instride,
                              const float* __restrict__ wgt,
                              const float* __restrict__ bias, float* __restrict__ out,
                              int Cn, int addin) {
    __shared__ float4 tile[12 * 12 * 4];
    __shared__ float wsm[16][26];
    const int tid = threadIdx.x;
    const int c4l = tid & 3, px = (tid >> 2) & 7, py = tid >> 5;
    const int c4b = blockIdx.y;
    const int gx0 = (blockIdx.x % 24) * 8, gy0 = (blockIdx.x / 24) * 8;

    for (int lw = tid; lw < 400; lw += 256)
        wsm[lw / 25][lw % 25] = wgt[(c4b * 16 + lw / 25) * 25 + lw % 25];

    for (int lin = tid; lin < 576; lin += 256) {
        int cc = lin & 3, rem = lin >> 2;
        int xx = rem % 12, yy = rem / 12;
        int gy = gy0 + yy - 2, gx = gx0 + xx - 2;
        float4 v = make_float4(0.f, 0.f, 0.f, 0.f);
        if ((unsigned)gy < (unsigned)IMG && (unsigned)gx < (unsigned)IMG)
            v = *(const float4*)(in + (size_t)(gy * IMG + gx) * instride + (c4b * 4 + cc) * 4);
        tile[(yy * 12 + xx) * 4 + cc] = v;
    }
    __syncthreads();

    float4 a = *(const float4*)(bias + (c4b * 4 + c4l) * 4);
    #pragma unroll
    for (int ky = 0; ky < 5; ky++) {
        #pragma unroll
        for (int kx = 0; kx < 5; kx++) {
            float4 v = tile[((py + ky) * 12 + px + kx) * 4 + c4l];
            int tp = ky * 5 + kx;
            a.x += v.x * wsm[c4l * 4 + 0][tp];
            a.y += v.y * wsm[c4l * 4 + 1][tp];
            a.z += v.z * wsm[c4l * 4 + 2][tp];
            a.w += v.w * wsm[c4l * 4 + 3][tp];
        }
    }
    float4 o;
    o.x = gelu_f(a.x); o.y = gelu_f(a.y); o.z = gelu_f(a.z); o.w = gelu_f(a.w);
    if (addin) {
        float4 iv = tile[((py + 2) * 12 + px + 2) * 4 + c4l];
        o.x += iv.x; o.y += iv.y; o.z += iv.z; o.w += iv.w;
    }
    *(float4*)(out + (size_t)((gy0 + py) * IMG + gx0 + px) * Cn + (c4b * 4 + c4l) * 4) = o;
}

// ---------------- attention v3: fp16 K/V smem, merged softmax/prior ----------
#define KHS 258
#define ATTN_SMEM_BYTES (2*16*KHS*4 + 128*256*4 + 128*260)
__global__ void attn_kernel(const float* __restrict__ qkv, const float* __restrict__ vl,
                            const float* __restrict__ pfa_v, const int* __restrict__ pfa_i,
                            const int* __restrict__ rpi, const float* __restrict__ rpb,
                            float* __restrict__ out) {
    extern __shared__ char smA[];
    __half2* kh = (__half2*)smA;                           // [p][j], stride KHS
    __half2* vh = kh + 16 * KHS;
    float* sc = (float*)(vh + 16 * KHS);                   // [kk][t]
    unsigned char* js = (unsigned char*)(sc + 128 * 256);  // [kk][260]

    const int t = threadIdx.x;
    const int h = blockIdx.x;
    const int w = blockIdx.y;
    const int wy = w / 12, wx = w % 12;
    const size_t whbase = ((size_t)w * NHEAD + h) * NTOK;

    const float* qg = qkv;
    const float* kg = qkv + 192;
    const float* vg = qkv + 384;

    #pragma unroll
    for (int rb = 0; rb < 256; rb += 32) {
        int r = rb + (t >> 3), e = t & 7;
        int pj = (wy * 16 + (r >> 4)) * IMG + wx * 16 + (r & 15);
        float4 kvl = *(const float4*)(kg + (size_t)pj * QKVN + h * 32 + e * 4);
        kh[(2 * e + 0) * KHS + r] = __floats2half2_rn(kvl.x, kvl.y);
        kh[(2 * e + 1) * KHS + r] = __floats2half2_rn(kvl.z, kvl.w);
        float4 vv4 = *(const float4*)(vg + (size_t)pj * QKVN + h * 32 + e * 4);
        vh[(2 * e + 0) * KHS + r] = __floats2half2_rn(vv4.x, vv4.y);
        vh[(2 * e + 1) * KHS + r] = __floats2half2_rn(vv4.z, vv4.w);
    }
    {
        const int* idxg = pfa_i + whbase * KINN;
        for (int e = t; e < NTOK * KINN; e += 256)
            js[(e & 127) * 260 + (e >> 7)] = (unsigned char)idxg[e];
    }
    __syncthreads();

    const int i = t;
    const int pi = (wy * 16 + (i >> 4)) * IMG + wx * 16 + (i & 15);

    float qreg[32];
    {
        const float4* qr = (const float4*)(qg + (size_t)pi * QKVN + h * 32);
        const float scl = 0.17677669529663688f;  // 1/sqrt(32)
        #pragma unroll
        for (int e = 0; e < 8; e++) {
            float4 a4 = qr[e];
            qreg[e * 4 + 0] = a4.x * scl; qreg[e * 4 + 1] = a4.y * scl;
            qreg[e * 4 + 2] = a4.z * scl; qreg[e * 4 + 3] = a4.w * scl;
        }
    }

    const int* rr = rpi + i * NTOK;
    float mx = -1e30f;
    #pragma unroll 2
    for (int kk = 0; kk < KINN; kk++) {
        int j = js[kk * 260 + t];
        float d = 0.f;
        #pragma unroll
        for (int p = 0; p < 16; p++) {
            float2 f = __half22float2(kh[p * KHS + j]);
            d += qreg[2 * p] * f.x + qreg[2 * p + 1] * f.y;
        }
        d += __ldg(&rpb[__ldg(&rr[j]) * NHEAD + h]);
        sc[kk * 256 + t] = d;
        mx = fmaxf(mx, d);
    }

    const float* pv = pfa_v + (whbase + i) * KINN;
    float sE = 0.f, sU = 0.f;
    float gmax[16];
    #pragma unroll
    for (int g = 0; g < 16; g++) {
        float gm = -3.f;
        #pragma unroll
        for (int e2 = 0; e2 < 8; e2 += 4) {
            int kk = g * 8 + e2;
            float4 p4 = *(const float4*)(pv + kk);
            float e0 = __expf(sc[(kk + 0) * 256 + t] - mx);
            float e1 = __expf(sc[(kk + 1) * 256 + t] - mx);
            float e2f = __expf(sc[(kk + 2) * 256 + t] - mx);
            float e3 = __expf(sc[(kk + 3) * 256 + t] - mx);
            sE += e0 + e1 + e2f + e3;
            float u0 = e0 * p4.x, u1 = e1 * p4.y, u2 = e2f * p4.z, u3 = e3 * p4.w;
            sc[(kk + 0) * 256 + t] = u0; sc[(kk + 1) * 256 + t] = u1;
            sc[(kk + 2) * 256 + t] = u2; sc[(kk + 3) * 256 + t] = u3;
            sU += u0 + u1 + u2 + u3;
            gm = fmaxf(gm, fmaxf(fmaxf(u0, u1), fmaxf(u2, u3)));
        }
        gmax[g] = gm;
    }
    const float epsE = 1e-10f * sE;
    const float r2 = 1.0f / (sU + epsE);

    float acc[32];
    #pragma unroll
    for (int dd = 0; dd < 32; dd++) acc[dd] = 0.f;
    for (int sel = 0; sel < TOPKN; sel++) {
        float best = gmax[0]; int bg = 0;
        #pragma unroll
        for (int g = 1; g < 16; g++)
            if (gmax[g] > best) { best = gmax[g]; bg = g; }
        float m1 = -3.f, m2 = -3.f; int be = 0;
        #pragma unroll
        for (int e2 = 0; e2 < 8; e2++) {
            float vv = sc[(bg * 8 + e2) * 256 + t];
            if (vv > m1) { m2 = m1; m1 = vv; be = e2; }
            else m2 = fmaxf(m2, vv);
        }
        int bkk = bg * 8 + be;
        sc[bkk * 256 + t] = -3.f;
        #pragma unroll
        for (int g = 0; g < 16; g++) if (g == bg) gmax[g] = m2;

        int j = js[bkk * 260 + t];
        float wv = (m1 + epsE) * r2;
        #pragma unroll
        for (int p = 0; p < 16; p++) {
            float2 f = __half22float2(vh[p * KHS + j]);
            acc[2 * p] += wv * f.x;
            acc[2 * p + 1] += wv * f.y;
        }
    }

    float* op = out + (size_t)pi * CCH + h * 32;
    const float* vp = vl + (size_t)pi * CCH + h * 32;
    #pragma unroll
    for (int e = 0; e < 8; e++) {
        float4 o;
        o.x = acc[e * 4 + 0] + vp[e * 4 + 0];
        o.y = acc[e * 4 + 1] + vp[e * 4 + 1];
        o.z = acc[e * 4 + 2] + vp[e * 4 + 2];
        o.w = acc[e * 4 + 3] + vp[e * 4 + 3];
        *(float4*)(op + e * 4) = o;
    }
}

// ---------------- launch ----------------
extern "C" void kernel_launch(void* const* d_in, const int* in_sizes, int n_in,
                              void* d_out, int out_size) {
    const float* features = (const float*)d_in[0];
    const float* pfa_v    = (const float*)d_in[1];
    const int*   pfa_i    = (const int*)  d_in[2];
    const int*   rpi      = (const int*)  d_in[3];
    const float* ln1_g    = (const float*)d_in[4];
    const float* ln1_b    = (const float*)d_in[5];
    const float* Wq_w     = (const float*)d_in[6];
    const float* Wq_b     = (const float*)d_in[7];
    const float* Wk_w     = (const float*)d_in[8];
    const float* Wk_b     = (const float*)d_in[9];
    const float* Wv_w     = (const float*)d_in[10];
    const float* Wv_b     = (const float*)d_in[11];
    const float* lepe_w   = (const float*)d_in[12];
    const float* lepe_b   = (const float*)d_in[13];
    const float* rpb_tab  = (const float*)d_in[14];
    const float* proj_w   = (const float*)d_in[15];
    const float* proj_b   = (const float*)d_in[16];
    const float* ln2_g    = (const float*)d_in[17];
    const float* ln2_b    = (const float*)d_in[18];
    const float* fc1_w    = (const float*)d_in[19];
    const float* fc1_b    = (const float*)d_in[20];
    const float* ffn_dw_w = (const float*)d_in[21];
    const float* ffn_dw_b = (const float*)d_in[22];
    const float* fc2_w    = (const float*)d_in[23];
    const float* fc2_b    = (const float*)d_in[24];
    float* outp = (float*)d_out;

    float *xn, *sct, *qkvb, *vlb, *attnb, *x2b, *ylnb, *ybb, *y2b, *bqkv;
    unsigned *wqkvh, *wprojh, *wfc1h, *wfc2h;
    cudaGetSymbolAddress((void**)&xn,    g_xn);
    cudaGetSymbolAddress((void**)&sct,   g_sct);
    cudaGetSymbolAddress((void**)&qkvb,  g_qkv);
    cudaGetSymbolAddress((void**)&vlb,   g_vl);
    cudaGetSymbolAddress((void**)&attnb, g_attn);
    cudaGetSymbolAddress((void**)&x2b,   g_x2);
    cudaGetSymbolAddress((void**)&ylnb,  g_yln);
    cudaGetSymbolAddress((void**)&ybb,   g_yb);
    cudaGetSymbolAddress((void**)&y2b,   g_y2);
    cudaGetSymbolAddress((void**)&wqkvh, g_wqkvh);
    cudaGetSymbolAddress((void**)&bqkv,  g_bqkv);
    cudaGetSymbolAddress((void**)&wprojh, g_wprojh);
    cudaGetSymbolAddress((void**)&wfc1h,  g_wfc1h);
    cudaGetSymbolAddress((void**)&wfc2h,  g_wfc2h);

    cudaFuncSetAttribute(attn_kernel, cudaFuncAttributeMaxDynamicSharedMemorySize,
                         ATTN_SMEM_BYTES);

    const int M = HW;

    // 0) weight prep: concat+pack QKV; pack proj/fc1/fc2 to half2 words
    qkv_prep_kernel<<<((CCH / 2) * QKVN + 255) / 256, 256>>>(
        Wq_w, Wk_w, Wv_w, Wq_b, Wk_b, Wv_b, wqkvh, bqkv);
    pack_half_kernel<<<((CCH / 2) * CCH + 255) / 256, 256>>>(proj_w, wprojh, CCH / 2, CCH);
    pack_half_kernel<<<((CCH / 2) * HIDN + 255) / 256, 256>>>(fc1_w, wfc1h, CCH / 2, HIDN);
    pack_half_kernel<<<((HIDN / 2) * CCH + 255) / 256, 256>>>(fc2_w, wfc2h, HIDN / 2, CCH);

    // 1) transpose + LN1 (+ raw transposed shortcut)
    ln1_kernel<<<HW / LNP, 256>>>(features, ln1_g, ln1_b, xn, sct);

    // 2) fused QKV projection: (HW,192) @ (192,576)
    hgemm_kernel<0, 0><<<dim3(3, M / 64), 128, GEMM_SMEM_BYTES>>>(
        xn, wqkvh, bqkv, qkvb, M, QKVN, CCH, nullptr);

    // 3) LePE: depthwise 5x5 + GELU on V slice of qkv
    dwconv_kernel<<<dim3(576, CCH / 16), 256>>>(qkvb + 384, QKVN, lepe_w, lepe_b,
                                                vlb, CCH, 0);

    // 4) sparse windowed attention (+vl)
    attn_kernel<<<dim3(NHEAD, NWIN), 256, ATTN_SMEM_BYTES>>>(
        qkvb, vlb, pfa_v, pfa_i, rpi, rpb_tab, attnb);

    // 5) output projection + shortcut (coalesced transposed residual)
    dim3 g192(1, M / 64);
    hgemm_kernel<0, 1><<<g192, 128, GEMM_SMEM_BYTES>>>(attnb, wprojh, proj_b, x2b,
                                                       M, CCH, CCH, sct);

    // 6) ConvFFN
    ln2_kernel<<<HW / 256, 256>>>(x2b, ln2_g, ln2_b, ylnb);
    hgemm_kernel<1, 0><<<dim3(4, M / 64), 128, GEMM_SMEM_BYTES>>>(
        ylnb, wfc1h, fc1_b, ybb, M, HIDN, CCH, nullptr);
    dwconv_kernel<<<dim3(576, HIDN / 16), 256>>>(ybb, HIDN, ffn_dw_w, ffn_dw_b,
                                                 y2b, HIDN, 1);
    hgemm_kernel<0, 1><<<g192, 128, GEMM_SMEM_BYTES>>>(y2b, wfc2h, fc2_b, outp,
                                                       M, CCH, HIDN, x2b);
    (void)in_sizes; (void)n_in; (void)out_size;
}